// round 1
// baseline (speedup 1.0000x reference)
#include <cuda_runtime.h>
#include <math.h>

// ---- problem dims ----
#define BB   4
#define LL   24
#define NNP  512
#define DIMC 1024
#define JJ   24
#define MMS  64
#define FDC  128
#define OUTC 72
#define NT   (LL*NNP)      // 12288 tokens per batch
#define TOK  (BB*NT)       // 49152 tokens total

#define SEG_OFF  (BB*OUTC)             // 288
#define SEG_SIZE (BB*LL*JJ*NNP)        // 1179648
#define LOSS_OFF (SEG_OFF + SEG_SIZE)  // 1179936

#define TB  64   // tokens per block in kernel B
#define KC  64   // memory-slot chunk (== M, so chunk index == joint index)
#define NBLK_B (BB*(NT/TB))            // 768

// ---- scratch (no allocations allowed; use device globals) ----
__device__ float    g_pc[(size_t)TOK*FDC];        // 25.2 MB pc features
__device__ float    g_lossPartial[NBLK_B];
__device__ unsigned g_skl[BB*FDC];

// ---- monotonic float<->uint encoding for atomicMax ----
__device__ __forceinline__ unsigned encf(float f) {
    unsigned u = __float_as_uint(f);
    return (u & 0x80000000u) ? ~u : (u | 0x80000000u);
}
__device__ __forceinline__ float decf(unsigned u) {
    return (u & 0x80000000u) ? __uint_as_float(u & 0x7FFFFFFFu)
                             : __uint_as_float(~u);
}

__global__ void kInit() {
    int i = blockIdx.x*blockDim.x + threadIdx.x;
    if (i < BB*FDC) g_skl[i] = 0u;   // 0 < enc(x) for every finite float
}

// =====================================================================
// Kernel A: fused seg+pc projection.
//   X (49152 x 1024) @ W^T, W = [seg_w(24x1024); pc_w(128x1024)] -> 152 cols
//   seg cols -> softmax over 24 -> written transposed into d_out seg region
//   pc  cols -> +bias -> g_pc scratch
// Tile: 128 tokens x 160 (padded) cols, K-chunks of 32, 8x10 microtile.
// =====================================================================
__global__ __launch_bounds__(256) void kA(const float* __restrict__ feat,
        const float* __restrict__ seg_w, const float* __restrict__ seg_b,
        const float* __restrict__ pc_w,  const float* __restrict__ pc_b,
        float* __restrict__ out)
{
    __shared__ float Xs[32][129];   // [k][token], pad 129 -> conflict-free
    __shared__ float Ws[32][161];   // [k][col],  pad 161

    const int tid = threadIdx.x;
    const int tx  = tid & 15;       // col group
    const int ty  = tid >> 4;       // row group
    const int t0  = blockIdx.x * 128;

    float acc[8][10];
#pragma unroll
    for (int i = 0; i < 8; i++)
#pragma unroll
        for (int j = 0; j < 10; j++) acc[i][j] = 0.f;

    const int kk = tid & 31;
    const int r0 = tid >> 5;        // 0..7

    for (int k0 = 0; k0 < DIMC; k0 += 32) {
#pragma unroll
        for (int m = r0; m < 128; m += 8)
            Xs[kk][m] = feat[(size_t)(t0 + m)*DIMC + k0 + kk];
#pragma unroll
        for (int n = r0; n < 160; n += 8) {
            float v = 0.f;
            if (n < JJ)            v = seg_w[n*DIMC + k0 + kk];
            else if (n < JJ + FDC) v = pc_w[(n - JJ)*DIMC + k0 + kk];
            Ws[kk][n] = v;
        }
        __syncthreads();
#pragma unroll
        for (int q = 0; q < 32; ++q) {
            float xr[8], wc[10];
#pragma unroll
            for (int i = 0; i < 8; i++)  xr[i] = Xs[q][ty + 16*i];
#pragma unroll
            for (int j = 0; j < 10; j++) wc[j] = Ws[q][tx + 16*j];
#pragma unroll
            for (int i = 0; i < 8; i++)
#pragma unroll
                for (int j = 0; j < 10; j++)
                    acc[i][j] = fmaf(xr[i], wc[j], acc[i][j]);
        }
        __syncthreads();
    }

    // epilogue: seg logits -> smem (overlay Xs); pc -> global scratch
    float (*SegS)[25] = reinterpret_cast<float(*)[25]>(&Xs[0][0]);
#pragma unroll
    for (int i = 0; i < 8; i++) {
        const int m = ty + 16*i;
#pragma unroll
        for (int j = 0; j < 10; j++) {
            const int n = tx + 16*j;
            if (n < JJ) {
                SegS[m][n] = acc[i][j] + seg_b[n];
            } else if (n < JJ + FDC) {
                const int d = n - JJ;
                g_pc[(size_t)(t0 + m)*FDC + d] = acc[i][j] + pc_b[d];
            }
        }
    }
    __syncthreads();

    if (tid < 128) {
        const int m = tid;
        float mx = -INFINITY;
#pragma unroll
        for (int j = 0; j < JJ; j++) mx = fmaxf(mx, SegS[m][j]);
        float e[JJ];
        float s = 0.f;
#pragma unroll
        for (int j = 0; j < JJ; j++) { e[j] = expf(SegS[m][j] - mx); s += e[j]; }
        const float inv = 1.f / s;
        const int t = t0 + m;
        const int b = t / NT; const int rr = t % NT;
        const int l = rr / NNP; const int nn = rr % NNP;
        float* segout = out + SEG_OFF + ((size_t)(b*LL + l)*JJ)*NNP + nn;
#pragma unroll
        for (int j = 0; j < JJ; j++) segout[(size_t)j*NNP] = e[j]*inv;
    }
}

// =====================================================================
// Kernel B: forward_mem fused (flash-style online softmax over 1536 slots)
//   per block: one batch, 64 tokens. 24 chunks of 64 slots (chunk == joint).
//   logits GEMM (64x64x128) -> scale by seg -> online softmax update ->
//   rec GEMM (64x128x64) into register accumulators with rescale.
//   epilogue: loss partial (deterministic) + per-d block max -> atomicMax.
// =====================================================================
__global__ __launch_bounds__(256) void kB(const float* __restrict__ memw,
        const float* __restrict__ segp)
{
    extern __shared__ float sm[];
    float* pcS  = sm;                 // 64*129   [token][d]
    float* memS = pcS  + 64*129;      // 64*129   [kk][d]
    float* pS   = memS + 64*129;      // 64*65    [token][kk]
    float* segS = pS   + 64*65;       // 64*25    [token][j]
    float* mrun = segS + 64*25;       // 64
    float* lrun = mrun + 64;          // 64
    float* fsc  = lrun + 64;          // 64
    __shared__ float wsum[8];

    const int tid = threadIdx.x;
    const int tx  = tid & 15;
    const int ty  = tid >> 4;
    const int b   = blockIdx.x / (NT/TB);
    const int tb  = blockIdx.x % (NT/TB);
    const int n0  = tb * TB;

    const float* pcB = g_pc + ((size_t)b*NT + n0)*FDC;
    for (int idx = tid; idx < TB*FDC; idx += 256) {
        const int m = idx >> 7, d = idx & 127;
        pcS[m*129 + d] = pcB[m*FDC + d];
    }
    {
        const int l = n0 / NNP, nn0 = n0 % NNP;
        const float* sp = segp + ((size_t)(b*LL + l)*JJ)*NNP + nn0;
        for (int idx = tid; idx < TB*JJ; idx += 256) {
            const int j = idx / TB, m = idx % TB;
            segS[m*25 + j] = sp[(size_t)j*NNP + m];
        }
    }
    if (tid < TB) { mrun[tid] = -INFINITY; lrun[tid] = 0.f; }

    float r[4][8];
#pragma unroll
    for (int i = 0; i < 4; i++)
#pragma unroll
        for (int c = 0; c < 8; c++) r[i][c] = 0.f;
    __syncthreads();

    for (int ch = 0; ch < JJ; ++ch) {
        const int k0 = ch * KC;
        for (int idx = tid; idx < KC*FDC; idx += 256) {
            const int d = idx >> 6, kk = idx & 63;
            memS[kk*129 + d] = memw[(size_t)d*(JJ*MMS) + k0 + kk];
        }
        __syncthreads();

        // logits: 4 tokens x 4 slots per thread, dot over 128 dims
        float lg[4][4];
#pragma unroll
        for (int i = 0; i < 4; i++)
#pragma unroll
            for (int c = 0; c < 4; c++) lg[i][c] = 0.f;
        for (int d = 0; d < FDC; ++d) {
            float pv[4], mv[4];
#pragma unroll
            for (int i = 0; i < 4; i++) pv[i] = pcS[(ty*4 + i)*129 + d];
#pragma unroll
            for (int c = 0; c < 4; c++) mv[c] = memS[(tx + 16*c)*129 + d];
#pragma unroll
            for (int i = 0; i < 4; i++)
#pragma unroll
                for (int c = 0; c < 4; c++)
                    lg[i][c] = fmaf(pv[i], mv[c], lg[i][c]);
        }
        const float invs = 0.088388347648318447f;  // 1/sqrt(128)
#pragma unroll
        for (int i = 0; i < 4; i++) {
            const float s = segS[(ty*4 + i)*25 + ch] * invs;
#pragma unroll
            for (int c = 0; c < 4; c++)
                pS[(ty*4 + i)*65 + tx + 16*c] = lg[i][c]*s;
        }
        __syncthreads();

        // online-softmax bookkeeping: 4 threads per token
        {
            const int tok = tid >> 2, part = tid & 3;
            float* row = pS + tok*65 + part*16;
            float mloc = -INFINITY;
#pragma unroll
            for (int q = 0; q < 16; q++) mloc = fmaxf(mloc, row[q]);
            mloc = fmaxf(mloc, __shfl_xor_sync(0xffffffffu, mloc, 1));
            mloc = fmaxf(mloc, __shfl_xor_sync(0xffffffffu, mloc, 2));
            const float mold = mrun[tok];
            const float mnew = fmaxf(mold, mloc);
            float sloc = 0.f;
#pragma unroll
            for (int q = 0; q < 16; q++) {
                const float e = expf(row[q] - mnew);
                row[q] = e; sloc += e;
            }
            sloc += __shfl_xor_sync(0xffffffffu, sloc, 1);
            sloc += __shfl_xor_sync(0xffffffffu, sloc, 2);
            if (part == 0) {
                const float f = expf(mold - mnew);   // 0 on first chunk
                fsc[tok]  = f;
                lrun[tok] = lrun[tok]*f + sloc;
                mrun[tok] = mnew;
            }
        }
        __syncthreads();

        // rescale + rec GEMM: 4 tokens x 8 dims per thread
        float fs[4];
#pragma unroll
        for (int i = 0; i < 4; i++) fs[i] = fsc[ty*4 + i];
#pragma unroll
        for (int i = 0; i < 4; i++)
#pragma unroll
            for (int c = 0; c < 8; c++) r[i][c] *= fs[i];
        for (int kkk = 0; kkk < KC; ++kkk) {
            float pv[4], mv[8];
#pragma unroll
            for (int i = 0; i < 4; i++) pv[i] = pS[(ty*4 + i)*65 + kkk];
#pragma unroll
            for (int c = 0; c < 8; c++) mv[c] = memS[kkk*129 + tx + 16*c];
#pragma unroll
            for (int i = 0; i < 4; i++)
#pragma unroll
                for (int c = 0; c < 8; c++)
                    r[i][c] = fmaf(pv[i], mv[c], r[i][c]);
        }
        __syncthreads();   // protect memS/pS for next chunk
    }

    // epilogue: normalize, loss partial, per-d max
    float linv[4];
#pragma unroll
    for (int i = 0; i < 4; i++) linv[i] = 1.f / lrun[ty*4 + i];
    float lossloc = 0.f;
    float rmax[8];
#pragma unroll
    for (int c = 0; c < 8; c++) rmax[c] = -INFINITY;
#pragma unroll
    for (int i = 0; i < 4; i++) {
#pragma unroll
        for (int c = 0; c < 8; c++) {
            const float rf   = r[i][c]*linv[i];
            const float diff = rf - pcS[(ty*4 + i)*129 + tx + 16*c];
            lossloc += diff*diff;
            rmax[c] = fmaxf(rmax[c], rf);
        }
    }
    // block max per d via smem (reuse pS; all threads past rec GEMM already)
#pragma unroll
    for (int c = 0; c < 8; c++) pS[ty*129 + tx + 16*c] = rmax[c];
    __syncthreads();
    if (tid < FDC) {
        float mx = -INFINITY;
#pragma unroll
        for (int t2 = 0; t2 < 16; t2++) mx = fmaxf(mx, pS[t2*129 + tid]);
        atomicMax(&g_skl[b*FDC + tid], encf(mx));
    }
#pragma unroll
    for (int o = 16; o > 0; o >>= 1)
        lossloc += __shfl_xor_sync(0xffffffffu, lossloc, o);
    if ((tid & 31) == 0) wsum[tid >> 5] = lossloc;
    __syncthreads();
    if (tid == 0) {
        float s = 0.f;
        for (int w = 0; w < 8; w++) s += wsum[w];
        g_lossPartial[blockIdx.x] = s;
    }
}

// =====================================================================
// Kernel C: finalize loss + skl head (LN -> Linear -> GELU -> Linear)
// =====================================================================
__global__ __launch_bounds__(256) void kC(const float* __restrict__ ln_g,
        const float* __restrict__ ln_b, const float* __restrict__ w1,
        const float* __restrict__ b1,   const float* __restrict__ w2,
        const float* __restrict__ b2,   float* __restrict__ out)
{
    __shared__ float red[128];
    __shared__ float hbuf[128];
    __shared__ float h2[64];
    __shared__ float wsum2[8];
    const int tid = threadIdx.x;

    // loss (deterministic two-stage sum)
    float s = 0.f;
    for (int i = tid; i < NBLK_B; i += 256) s += g_lossPartial[i];
#pragma unroll
    for (int o = 16; o > 0; o >>= 1) s += __shfl_xor_sync(0xffffffffu, s, o);
    if ((tid & 31) == 0) wsum2[tid >> 5] = s;
    __syncthreads();
    if (tid == 0) {
        float t = 0.f;
        for (int w = 0; w < 8; w++) t += wsum2[w];
        out[LOSS_OFF] = t / ((float)TOK * (float)FDC);
    }

    for (int b = 0; b < BB; ++b) {
        float x = 0.f;
        if (tid < FDC) { x = decf(g_skl[b*FDC + tid]); red[tid] = x; }
        __syncthreads();
        for (int o = 64; o > 0; o >>= 1) {
            if (tid < o) red[tid] += red[tid + o];
            __syncthreads();
        }
        const float mu = red[0] * (1.f/FDC);
        __syncthreads();
        const float dfx = x - mu;
        if (tid < FDC) red[tid] = dfx*dfx;
        __syncthreads();
        for (int o = 64; o > 0; o >>= 1) {
            if (tid < o) red[tid] += red[tid + o];
            __syncthreads();
        }
        const float var = red[0] * (1.f/FDC);
        __syncthreads();
        if (tid < FDC)
            hbuf[tid] = dfx * rsqrtf(var + 1e-5f) * ln_g[tid] + ln_b[tid];
        __syncthreads();
        if (tid < FDC/2) {
            float a = b1[tid];
            for (int d = 0; d < FDC; ++d) a = fmaf(hbuf[d], w1[tid*FDC + d], a);
            h2[tid] = 0.5f * a * (1.f + erff(a * 0.70710678118654752f));
        }
        __syncthreads();
        if (tid < OUTC) {
            float a = b2[tid];
            for (int e = 0; e < FDC/2; ++e) a = fmaf(h2[e], w2[tid*(FDC/2) + e], a);
            out[b*OUTC + tid] = a;
        }
        __syncthreads();
    }
}

extern "C" void kernel_launch(void* const* d_in, const int* in_sizes, int n_in,
                              void* d_out, int out_size)
{
    const float* feat  = (const float*)d_in[0];
    const float* seg_w = (const float*)d_in[1];
    const float* seg_b = (const float*)d_in[2];
    const float* pc_w  = (const float*)d_in[3];
    const float* pc_b  = (const float*)d_in[4];
    const float* memw  = (const float*)d_in[5];
    const float* ln_g  = (const float*)d_in[6];
    const float* ln_b  = (const float*)d_in[7];
    const float* w1    = (const float*)d_in[8];
    const float* b1    = (const float*)d_in[9];
    const float* w2    = (const float*)d_in[10];
    const float* b2    = (const float*)d_in[11];
    float* out = (float*)d_out;

    const int smemB = (64*129 + 64*129 + 64*65 + 64*25 + 64*3) * 4;  // 89856
    cudaFuncSetAttribute(kB, cudaFuncAttributeMaxDynamicSharedMemorySize, smemB);

    kInit<<<1, 512>>>();
    kA<<<TOK/128, 256>>>(feat, seg_w, seg_b, pc_w, pc_b, out);
    kB<<<NBLK_B, 256, smemB>>>(memw, out + SEG_OFF);
    kC<<<1, 256>>>(ln_g, ln_b, w1, b1, w2, b2, out);
}

// round 3
// speedup vs baseline: 2.5773x; 2.5773x over previous
#include <cuda_runtime.h>
#include <cuda_bf16.h>
#include <math.h>
#include <cstdint>

// ---- problem dims ----
#define BB   4
#define LL   24
#define NNP  512
#define DIMC 1024
#define JJ   24
#define MMS  64
#define FDC  128
#define OUTC 72
#define NT   (LL*NNP)      // 12288 tokens per batch
#define TOK  (BB*NT)       // 49152 tokens total

#define SEG_OFF  (BB*OUTC)             // 288
#define SEG_SIZE (BB*LL*JJ*NNP)        // 1179648
#define LOSS_OFF (SEG_OFF + SEG_SIZE)  // 1179936

#define TBB 128
#define NBLK_B (BB*(NT/TBB))           // 384

// ---- device scratch ----
__device__ __nv_bfloat16 g_pc_hi[(size_t)TOK*FDC];
__device__ __nv_bfloat16 g_pc_lo[(size_t)TOK*FDC];
__device__ __nv_bfloat16 g_memT_hi[JJ*MMS*FDC];   // [slot][d]
__device__ __nv_bfloat16 g_memT_lo[JJ*MMS*FDC];
__device__ __nv_bfloat16 g_mem_hi[FDC*JJ*MMS];    // [d][slot]
__device__ __nv_bfloat16 g_mem_lo[FDC*JJ*MMS];
__device__ float    g_lossPartial[NBLK_B];
__device__ unsigned g_skl[BB*FDC];

// ---- monotonic float<->uint encoding for atomicMax ----
__device__ __forceinline__ unsigned encf(float f) {
    unsigned u = __float_as_uint(f);
    return (u & 0x80000000u) ? ~u : (u | 0x80000000u);
}
__device__ __forceinline__ float decf(unsigned u) {
    return (u & 0x80000000u) ? __uint_as_float(u & 0x7FFFFFFFu)
                             : __uint_as_float(~u);
}

// ---- mma.sync m16n8k16 bf16 (register accumulators) ----
__device__ __forceinline__ void mma16816(float* d, uint32_t a0, uint32_t a1,
                                         uint32_t a2, uint32_t a3,
                                         uint32_t b0, uint32_t b1) {
    asm volatile("mma.sync.aligned.m16n8k16.row.col.f32.bf16.bf16.f32 "
        "{%0,%1,%2,%3}, {%4,%5,%6,%7}, {%8,%9}, {%0,%1,%2,%3};"
        : "+f"(d[0]), "+f"(d[1]), "+f"(d[2]), "+f"(d[3])
        : "r"(a0), "r"(a1), "r"(a2), "r"(a3), "r"(b0), "r"(b1));
}
// A fragment (m16 x k16, row-major in smem, stride in bf16 elems)
__device__ __forceinline__ void ldA(uint32_t* a, const __nv_bfloat16* base,
                                    int row, int k, int stride, int lane) {
    const __nv_bfloat16* p = base + (size_t)(row + (lane >> 2))*stride + k + (lane & 3)*2;
    a[0] = *(const uint32_t*)p;
    a[1] = *(const uint32_t*)(p + 8*stride);
    a[2] = *(const uint32_t*)(p + 8);
    a[3] = *(const uint32_t*)(p + 8*stride + 8);
}
// B fragment (k16 x n8, stored as BT[n][k] row-major)
__device__ __forceinline__ void ldB(uint32_t* b, const __nv_bfloat16* base,
                                    int n, int k, int stride, int lane) {
    const __nv_bfloat16* p = base + (size_t)(n + (lane >> 2))*stride + k + (lane & 3)*2;
    b[0] = *(const uint32_t*)p;
    b[1] = *(const uint32_t*)(p + 8);
}
__device__ __forceinline__ void hilo(float v, __nv_bfloat16& h, __nv_bfloat16& l) {
    h = __float2bfloat16(v);
    l = __float2bfloat16(v - __bfloat162float(h));
}

__global__ void kInit() {
    int i = blockIdx.x*blockDim.x + threadIdx.x;
    if (i < BB*FDC) g_skl[i] = 0u;
}

// pre-convert mem into bf16 hi/lo, both layouts
__global__ void kPrep(const float* __restrict__ memw) {
    int i = blockIdx.x*blockDim.x + threadIdx.x;
    if (i >= FDC*JJ*MMS) return;
    int d = i / (JJ*MMS), k = i % (JJ*MMS);
    float v = memw[i];
    __nv_bfloat16 h, l; hilo(v, h, l);
    g_mem_hi[i] = h;  g_mem_lo[i] = l;
    g_memT_hi[k*FDC + d] = h;  g_memT_lo[k*FDC + d] = l;
}

// =====================================================================
// Kernel A: fused seg+pc projection on HMMA (bf16 hi/lo 3-pass)
//   block: 128 tokens x 160 cols (24 seg + 128 pc + 8 pad), 8 warps 4m x 2n
// =====================================================================
#define KA_AS 40    // A tile row stride (bf16): k=32 + pad 8
#define KA_WS 40
__global__ __launch_bounds__(256) void kA(const float* __restrict__ feat,
        const float* __restrict__ seg_w, const float* __restrict__ seg_b,
        const float* __restrict__ pc_w,  const float* __restrict__ pc_b,
        float* __restrict__ out)
{
    __shared__ __nv_bfloat16 AsH[128*KA_AS], AsL[128*KA_AS];
    __shared__ __nv_bfloat16 WsH[160*KA_WS], WsL[160*KA_WS];

    const int tid  = threadIdx.x;
    const int lane = tid & 31;
    const int wid  = tid >> 5;
    const int wm   = wid >> 1, wn = wid & 1;
    const int row0 = wm*32, col0 = wn*80;
    const int t0   = blockIdx.x * 128;

    float acc[2][10][4];
#pragma unroll
    for (int mt = 0; mt < 2; mt++)
#pragma unroll
        for (int nt = 0; nt < 10; nt++)
#pragma unroll
            for (int r = 0; r < 4; r++) acc[mt][nt][r] = 0.f;

    for (int k0 = 0; k0 < DIMC; k0 += 32) {
        // load+convert feat tile: 128 x 32
#pragma unroll
        for (int it = 0; it < 4; it++) {
            const int p = tid + it*256;           // 0..1023
            const int r = p >> 3, c4 = (p & 7)*4;
            const float4 v = *(const float4*)&feat[(size_t)(t0 + r)*DIMC + k0 + c4];
            __nv_bfloat16 h0,l0,h1,l1,h2,l2,h3,l3;
            hilo(v.x,h0,l0); hilo(v.y,h1,l1); hilo(v.z,h2,l2); hilo(v.w,h3,l3);
            __nv_bfloat162* dh = (__nv_bfloat162*)&AsH[r*KA_AS + c4];
            __nv_bfloat162* dl = (__nv_bfloat162*)&AsL[r*KA_AS + c4];
            dh[0] = __nv_bfloat162{h0,h1}; dh[1] = __nv_bfloat162{h2,h3};
            dl[0] = __nv_bfloat162{l0,l1}; dl[1] = __nv_bfloat162{l2,l3};
        }
        // load+convert W tile: 160 x 32 (rows 0..23 seg_w, 24..151 pc_w, rest 0)
#pragma unroll
        for (int it = 0; it < 5; it++) {
            const int p = tid + it*256;           // 0..1279
            const int r = p >> 3, c4 = (p & 7)*4;
            float4 v = make_float4(0.f,0.f,0.f,0.f);
            if (r < JJ)            v = *(const float4*)&seg_w[(size_t)r*DIMC + k0 + c4];
            else if (r < JJ + FDC) v = *(const float4*)&pc_w[(size_t)(r - JJ)*DIMC + k0 + c4];
            __nv_bfloat16 h0,l0,h1,l1,h2,l2,h3,l3;
            hilo(v.x,h0,l0); hilo(v.y,h1,l1); hilo(v.z,h2,l2); hilo(v.w,h3,l3);
            __nv_bfloat162* dh = (__nv_bfloat162*)&WsH[r*KA_WS + c4];
            __nv_bfloat162* dl = (__nv_bfloat162*)&WsL[r*KA_WS + c4];
            dh[0] = __nv_bfloat162{h0,h1}; dh[1] = __nv_bfloat162{h2,h3};
            dl[0] = __nv_bfloat162{l0,l1}; dl[1] = __nv_bfloat162{l2,l3};
        }
        __syncthreads();
#pragma unroll
        for (int ks = 0; ks < 2; ks++) {
            const int kk = ks*16;
            uint32_t ah[2][4], al[2][4];
            ldA(ah[0], AsH, row0,      kk, KA_AS, lane);
            ldA(ah[1], AsH, row0 + 16, kk, KA_AS, lane);
            ldA(al[0], AsL, row0,      kk, KA_AS, lane);
            ldA(al[1], AsL, row0 + 16, kk, KA_AS, lane);
#pragma unroll
            for (int nt = 0; nt < 10; nt++) {
                uint32_t bh[2], bl[2];
                ldB(bh, WsH, col0 + nt*8, kk, KA_WS, lane);
                ldB(bl, WsL, col0 + nt*8, kk, KA_WS, lane);
#pragma unroll
                for (int mt = 0; mt < 2; mt++) {
                    mma16816(acc[mt][nt], ah[mt][0],ah[mt][1],ah[mt][2],ah[mt][3], bh[0],bh[1]);
                    mma16816(acc[mt][nt], ah[mt][0],ah[mt][1],ah[mt][2],ah[mt][3], bl[0],bl[1]);
                    mma16816(acc[mt][nt], al[mt][0],al[mt][1],al[mt][2],al[mt][3], bh[0],bh[1]);
                }
            }
        }
        __syncthreads();
    }

    const int lq = lane >> 2, lr = lane & 3;
    // ---- pc epilogue: cols 24..151 -> g_pc hi/lo ----
#pragma unroll
    for (int mt = 0; mt < 2; mt++)
#pragma unroll
        for (int nt = 0; nt < 10; nt++) {
            const int c0 = col0 + nt*8 + lr*2;
            if (c0 < 24 || c0 >= 152) continue;
            const int d = c0 - 24;
#pragma unroll
            for (int half = 0; half < 2; half++) {
                const int token = t0 + row0 + mt*16 + lq + half*8;
                const float v0 = acc[mt][nt][half*2 + 0] + pc_b[d];
                const float v1 = acc[mt][nt][half*2 + 1] + pc_b[d + 1];
                __nv_bfloat16 h0,l0,h1,l1;
                hilo(v0,h0,l0); hilo(v1,h1,l1);
                *(__nv_bfloat162*)&g_pc_hi[(size_t)token*FDC + d] = __nv_bfloat162{h0,h1};
                *(__nv_bfloat162*)&g_pc_lo[(size_t)token*FDC + d] = __nv_bfloat162{l0,l1};
            }
        }
    // ---- seg epilogue: cols 0..23 live in wn==0 warps, n-tiles 0..2 ----
    if (wn == 0) {
#pragma unroll
        for (int mt = 0; mt < 2; mt++)
#pragma unroll
            for (int half = 0; half < 2; half++) {
                const int row = row0 + mt*16 + lq + half*8;
                float v[6];
#pragma unroll
                for (int nt = 0; nt < 3; nt++)
#pragma unroll
                    for (int q = 0; q < 2; q++)
                        v[nt*2 + q] = acc[mt][nt][half*2 + q] + seg_b[nt*8 + lr*2 + q];
                float mx = v[0];
#pragma unroll
                for (int q = 1; q < 6; q++) mx = fmaxf(mx, v[q]);
                mx = fmaxf(mx, __shfl_xor_sync(0xffffffffu, mx, 1));
                mx = fmaxf(mx, __shfl_xor_sync(0xffffffffu, mx, 2));
                float s = 0.f;
#pragma unroll
                for (int q = 0; q < 6; q++) { v[q] = expf(v[q] - mx); s += v[q]; }
                s += __shfl_xor_sync(0xffffffffu, s, 1);
                s += __shfl_xor_sync(0xffffffffu, s, 2);
                const float inv = 1.f / s;
                const int t = t0 + row;
                const int b = t / NT; const int rr = t % NT;
                const int l = rr / NNP; const int nn = rr % NNP;
                float* segout = out + SEG_OFF + ((size_t)(b*LL + l)*JJ)*NNP + nn;
#pragma unroll
                for (int nt = 0; nt < 3; nt++)
#pragma unroll
                    for (int q = 0; q < 2; q++)
                        segout[(size_t)(nt*8 + lr*2 + q)*NNP] = v[nt*2 + q]*inv;
            }
    }
}

// =====================================================================
// Kernel B: forward_mem on HMMA (bf16 hi/lo 3-pass, no-shift softmax)
// =====================================================================
#define S_A1 136   // pc / memT tile stride (k=128 + pad 8)
#define S_K64 72   // attn / mem tile stride (k=64 + pad 8)
#define OFF_A1H  0
#define OFF_A1L  34816
#define OFF_B1H  69632
#define OFF_B1L  87040
#define OFF_B2H  104448
#define OFF_B2L  122880
#define OFF_A2H  141312
#define OFF_A2L  159744
#define OFF_SEG  178176
#define OFF_PSUM 190976
#define OFF_DMAX 192000
#define OFF_WSUM 192512
#define SMEM_B_TOTAL 192544

__global__ __launch_bounds__(256) void kB(const float* __restrict__ segp)
{
    extern __shared__ char sm[];
    __nv_bfloat16* A1H = (__nv_bfloat16*)(sm + OFF_A1H);
    __nv_bfloat16* A1L = (__nv_bfloat16*)(sm + OFF_A1L);
    __nv_bfloat16* B1H = (__nv_bfloat16*)(sm + OFF_B1H);
    __nv_bfloat16* B1L = (__nv_bfloat16*)(sm + OFF_B1L);
    __nv_bfloat16* B2H = (__nv_bfloat16*)(sm + OFF_B2H);
    __nv_bfloat16* B2L = (__nv_bfloat16*)(sm + OFF_B2L);
    __nv_bfloat16* A2H = (__nv_bfloat16*)(sm + OFF_A2H);
    __nv_bfloat16* A2L = (__nv_bfloat16*)(sm + OFF_A2L);
    float*    segS  = (float*)(sm + OFF_SEG);      // [tok][25]
    float*    psumS = (float*)(sm + OFF_PSUM);     // [2][128]
    unsigned* dmax  = (unsigned*)(sm + OFF_DMAX);  // [128]
    float*    wsum  = (float*)(sm + OFF_WSUM);

    const int tid  = threadIdx.x;
    const int lane = tid & 31;
    const int wid  = tid >> 5;
    const int wm   = wid >> 1, wn = wid & 1;
    const int row0 = wm*32;
    const int lq = lane >> 2, lr = lane & 3;
    const int b   = blockIdx.x / (NT/TBB);
    const int n0  = (blockIdx.x % (NT/TBB)) * TBB;

    // A1: pc tile (128 x 128 hi/lo)
    {
        const size_t base = ((size_t)b*NT + n0)*FDC;
#pragma unroll
        for (int it = 0; it < 32; it++) {
            const int p = tid + it*256;            // 0..8191 pairs
            const int r = p >> 6, c2 = (p & 63)*2;
            *(__nv_bfloat162*)&A1H[r*S_A1 + c2] = *(const __nv_bfloat162*)&g_pc_hi[base + (size_t)r*FDC + c2];
            *(__nv_bfloat162*)&A1L[r*S_A1 + c2] = *(const __nv_bfloat162*)&g_pc_lo[base + (size_t)r*FDC + c2];
        }
    }
    // seg tile [tok][j] (source is [j][tok])
    {
        const int l = n0 / NNP, nn0 = n0 % NNP;
        const float* sp = segp + ((size_t)(b*LL + l)*JJ)*NNP + nn0;
        for (int idx = tid; idx < TBB*JJ; idx += 256) {
            const int j = idx >> 7, m = idx & 127;
            segS[m*25 + j] = sp[(size_t)j*NNP + m];
        }
    }
    if (tid < FDC) dmax[tid] = 0u;

    float racc[2][8][4];
#pragma unroll
    for (int mt = 0; mt < 2; mt++)
#pragma unroll
        for (int nt = 0; nt < 8; nt++)
#pragma unroll
            for (int r = 0; r < 4; r++) racc[mt][nt][r] = 0.f;
    float psum_r[4] = {0.f, 0.f, 0.f, 0.f};
    const float invs = 0.088388347648318447f;  // 1/sqrt(128)

    for (int ch = 0; ch < JJ; ++ch) {
        const int k0 = ch*MMS;
        __syncthreads();   // prev-chunk rec mma done before overwriting B tiles
        // B1: memT chunk [slot][d] 64 x 128
#pragma unroll
        for (int it = 0; it < 16; it++) {
            const int p = tid + it*256;            // 0..4095 pairs
            const int r = p >> 6, c2 = (p & 63)*2;
            *(__nv_bfloat162*)&B1H[r*S_A1 + c2] = *(const __nv_bfloat162*)&g_memT_hi[(k0 + r)*FDC + c2];
            *(__nv_bfloat162*)&B1L[r*S_A1 + c2] = *(const __nv_bfloat162*)&g_memT_lo[(k0 + r)*FDC + c2];
        }
        // B2: mem chunk [d][slot] 128 x 64
#pragma unroll
        for (int it = 0; it < 16; it++) {
            const int p = tid + it*256;
            const int r = p >> 5, c2 = (p & 31)*2;
            *(__nv_bfloat162*)&B2H[r*S_K64 + c2] = *(const __nv_bfloat162*)&g_mem_hi[(size_t)r*(JJ*MMS) + k0 + c2];
            *(__nv_bfloat162*)&B2L[r*S_K64 + c2] = *(const __nv_bfloat162*)&g_mem_lo[(size_t)r*(JJ*MMS) + k0 + c2];
        }
        __syncthreads();

        // logits: 128 tok x 64 slots, K=128 (warp tile 32 x 32)
        float lacc[2][4][4];
#pragma unroll
        for (int mt = 0; mt < 2; mt++)
#pragma unroll
            for (int nt = 0; nt < 4; nt++)
#pragma unroll
                for (int r = 0; r < 4; r++) lacc[mt][nt][r] = 0.f;
#pragma unroll
        for (int ks = 0; ks < 8; ks++) {
            const int kk = ks*16;
            uint32_t ah[2][4], al[2][4];
            ldA(ah[0], A1H, row0,      kk, S_A1, lane);
            ldA(ah[1], A1H, row0 + 16, kk, S_A1, lane);
            ldA(al[0], A1L, row0,      kk, S_A1, lane);
            ldA(al[1], A1L, row0 + 16, kk, S_A1, lane);
#pragma unroll
            for (int nt = 0; nt < 4; nt++) {
                uint32_t bh[2], bl[2];
                ldB(bh, B1H, wn*32 + nt*8, kk, S_A1, lane);
                ldB(bl, B1L, wn*32 + nt*8, kk, S_A1, lane);
#pragma unroll
                for (int mt = 0; mt < 2; mt++) {
                    mma16816(lacc[mt][nt], ah[mt][0],ah[mt][1],ah[mt][2],ah[mt][3], bh[0],bh[1]);
                    mma16816(lacc[mt][nt], ah[mt][0],ah[mt][1],ah[mt][2],ah[mt][3], bl[0],bl[1]);
                    mma16816(lacc[mt][nt], al[mt][0],al[mt][1],al[mt][2],al[mt][3], bh[0],bh[1]);
                }
            }
        }
        // exp + psum + store attn hi/lo
#pragma unroll
        for (int mt = 0; mt < 2; mt++)
#pragma unroll
            for (int half = 0; half < 2; half++) {
                const int row = row0 + mt*16 + lq + half*8;
                const float sv = segS[row*25 + ch] * invs;
#pragma unroll
                for (int nt = 0; nt < 4; nt++) {
                    const float p0 = __expf(lacc[mt][nt][half*2 + 0] * sv);
                    const float p1 = __expf(lacc[mt][nt][half*2 + 1] * sv);
                    psum_r[mt*2 + half] += p0 + p1;
                    __nv_bfloat16 h0,l0,h1,l1;
                    hilo(p0,h0,l0); hilo(p1,h1,l1);
                    const int s0 = wn*32 + nt*8 + lr*2;
                    *(__nv_bfloat162*)&A2H[row*S_K64 + s0] = __nv_bfloat162{h0,h1};
                    *(__nv_bfloat162*)&A2L[row*S_K64 + s0] = __nv_bfloat162{l0,l1};
                }
            }
        __syncthreads();

        // rec: 128 tok x 128 dims, K=64 (warp tile 32 x 64), accumulate over chunks
#pragma unroll
        for (int ks = 0; ks < 4; ks++) {
            const int kk = ks*16;
            uint32_t ah[2][4], al[2][4];
            ldA(ah[0], A2H, row0,      kk, S_K64, lane);
            ldA(ah[1], A2H, row0 + 16, kk, S_K64, lane);
            ldA(al[0], A2L, row0,      kk, S_K64, lane);
            ldA(al[1], A2L, row0 + 16, kk, S_K64, lane);
#pragma unroll
            for (int nt = 0; nt < 8; nt++) {
                uint32_t bh[2], bl[2];
                ldB(bh, B2H, wn*64 + nt*8, kk, S_K64, lane);
                ldB(bl, B2L, wn*64 + nt*8, kk, S_K64, lane);
#pragma unroll
                for (int mt = 0; mt < 2; mt++) {
                    mma16816(racc[mt][nt], ah[mt][0],ah[mt][1],ah[mt][2],ah[mt][3], bh[0],bh[1]);
                    mma16816(racc[mt][nt], ah[mt][0],ah[mt][1],ah[mt][2],ah[mt][3], bl[0],bl[1]);
                    mma16816(racc[mt][nt], al[mt][0],al[mt][1],al[mt][2],al[mt][3], bh[0],bh[1]);
                }
            }
        }
    }

    // psum: quad-reduce then combine the two wn halves
#pragma unroll
    for (int i = 0; i < 4; i++) {
        psum_r[i] += __shfl_xor_sync(0xffffffffu, psum_r[i], 1);
        psum_r[i] += __shfl_xor_sync(0xffffffffu, psum_r[i], 2);
    }
    __syncthreads();
    if (lr == 0) {
#pragma unroll
        for (int i = 0; i < 4; i++) {
            const int row = row0 + (i >> 1)*16 + lq + (i & 1)*8;
            psumS[wn*128 + row] = psum_r[i];
        }
    }
    __syncthreads();

    // epilogue: normalize rec, loss, per-dim max
    float lossloc = 0.f;
#pragma unroll
    for (int mt = 0; mt < 2; mt++)
#pragma unroll
        for (int half = 0; half < 2; half++) {
            const int row = row0 + mt*16 + lq + half*8;
            const float inv = 1.f / (psumS[row] + psumS[128 + row]);
#pragma unroll
            for (int nt = 0; nt < 8; nt++) {
                const int c0 = wn*64 + nt*8 + lr*2;
                const float r0 = racc[mt][nt][half*2 + 0]*inv;
                const float r1 = racc[mt][nt][half*2 + 1]*inv;
                const __nv_bfloat162 ph = *(const __nv_bfloat162*)&A1H[row*S_A1 + c0];
                const __nv_bfloat162 pl = *(const __nv_bfloat162*)&A1L[row*S_A1 + c0];
                const float d0 = r0 - (__bfloat162float(ph.x) + __bfloat162float(pl.x));
                const float d1 = r1 - (__bfloat162float(ph.y) + __bfloat162float(pl.y));
                lossloc += d0*d0 + d1*d1;
                atomicMax(&dmax[c0],     encf(r0));
                atomicMax(&dmax[c0 + 1], encf(r1));
            }
        }
    __syncthreads();
    if (tid < FDC) atomicMax(&g_skl[b*FDC + tid], dmax[tid]);
#pragma unroll
    for (int o = 16; o > 0; o >>= 1)
        lossloc += __shfl_xor_sync(0xffffffffu, lossloc, o);
    if (lane == 0) wsum[wid] = lossloc;
    __syncthreads();
    if (tid == 0) {
        float s = 0.f;
        for (int w = 0; w < 8; w++) s += wsum[w];
        g_lossPartial[blockIdx.x] = s;
    }
}

// =====================================================================
// Kernel C: finalize loss + skl head (LN -> Linear -> GELU -> Linear)
// =====================================================================
__global__ __launch_bounds__(256) void kC(const float* __restrict__ ln_g,
        const float* __restrict__ ln_b, const float* __restrict__ w1,
        const float* __restrict__ b1,   const float* __restrict__ w2,
        const float* __restrict__ b2,   float* __restrict__ out)
{
    __shared__ float red[128];
    __shared__ float hbuf[128];
    __shared__ float h2[64];
    __shared__ float wsum2[8];
    const int tid = threadIdx.x;

    float s = 0.f;
    for (int i = tid; i < NBLK_B; i += 256) s += g_lossPartial[i];
#pragma unroll
    for (int o = 16; o > 0; o >>= 1) s += __shfl_xor_sync(0xffffffffu, s, o);
    if ((tid & 31) == 0) wsum2[tid >> 5] = s;
    __syncthreads();
    if (tid == 0) {
        float t = 0.f;
        for (int w = 0; w < 8; w++) t += wsum2[w];
        out[LOSS_OFF] = t / ((float)TOK * (float)FDC);
    }

    for (int b = 0; b < BB; ++b) {
        float x = 0.f;
        if (tid < FDC) { x = decf(g_skl[b*FDC + tid]); red[tid] = x; }
        __syncthreads();
        for (int o = 64; o > 0; o >>= 1) {
            if (tid < o) red[tid] += red[tid + o];
            __syncthreads();
        }
        const float mu = red[0] * (1.f/FDC);
        __syncthreads();
        const float dfx = x - mu;
        if (tid < FDC) red[tid] = dfx*dfx;
        __syncthreads();
        for (int o = 64; o > 0; o >>= 1) {
            if (tid < o) red[tid] += red[tid + o];
            __syncthreads();
        }
        const float var = red[0] * (1.f/FDC);
        __syncthreads();
        if (tid < FDC)
            hbuf[tid] = dfx * rsqrtf(var + 1e-5f) * ln_g[tid] + ln_b[tid];
        __syncthreads();
        if (tid < FDC/2) {
            float a = b1[tid];
            for (int d = 0; d < FDC; ++d) a = fmaf(hbuf[d], w1[tid*FDC + d], a);
            h2[tid] = 0.5f * a * (1.f + erff(a * 0.70710678118654752f));
        }
        __syncthreads();
        if (tid < OUTC) {
            float a = b2[tid];
            for (int e = 0; e < FDC/2; ++e) a = fmaf(h2[e], w2[tid*(FDC/2) + e], a);
            out[b*OUTC + tid] = a;
        }
        __syncthreads();
    }
}

extern "C" void kernel_launch(void* const* d_in, const int* in_sizes, int n_in,
                              void* d_out, int out_size)
{
    const float* feat  = (const float*)d_in[0];
    const float* seg_w = (const float*)d_in[1];
    const float* seg_b = (const float*)d_in[2];
    const float* pc_w  = (const float*)d_in[3];
    const float* pc_b  = (const float*)d_in[4];
    const float* memw  = (const float*)d_in[5];
    const float* ln_g  = (const float*)d_in[6];
    const float* ln_b  = (const float*)d_in[7];
    const float* w1    = (const float*)d_in[8];
    const float* b1    = (const float*)d_in[9];
    const float* w2    = (const float*)d_in[10];
    const float* b2    = (const float*)d_in[11];
    float* out = (float*)d_out;

    cudaFuncSetAttribute(kB, cudaFuncAttributeMaxDynamicSharedMemorySize, SMEM_B_TOTAL);

    kInit<<<1, 512>>>();
    kPrep<<<(FDC*JJ*MMS + 255)/256, 256>>>(memw);
    kA<<<TOK/128, 256>>>(feat, seg_w, seg_b, pc_w, pc_b, out);
    kB<<<NBLK_B, 256, SMEM_B_TOTAL>>>(out + SEG_OFF);
    kC<<<1, 256>>>(ln_g, ln_b, w1, b1, w2, b2, out);
}

// round 4
// speedup vs baseline: 3.2608x; 1.2652x over previous
#include <cuda_runtime.h>
#include <cuda_bf16.h>
#include <math.h>
#include <cstdint>

// ---- problem dims ----
#define BB   4
#define LL   24
#define NNP  512
#define DIMC 1024
#define JJ   24
#define MMS  64
#define FDC  128
#define OUTC 72
#define NT   (LL*NNP)
#define TOK  (BB*NT)

#define SEG_OFF  (BB*OUTC)
#define SEG_SIZE (BB*LL*JJ*NNP)
#define LOSS_OFF (SEG_OFF + SEG_SIZE)

#define TBB 128
#define NBLK_B (BB*(NT/TBB))           // 384

// ---- device scratch ----
__device__ __nv_bfloat16 g_pc_hi[(size_t)TOK*FDC];
__device__ __nv_bfloat16 g_pc_lo[(size_t)TOK*FDC];
__device__ __nv_bfloat16 g_mem_hi[FDC*JJ*MMS];    // [d][slot]
__device__ __nv_bfloat16 g_mem_lo[FDC*JJ*MMS];
__device__ float    g_lossPartial[NBLK_B];
__device__ unsigned g_skl[BB*FDC];

__device__ __forceinline__ unsigned encf(float f) {
    unsigned u = __float_as_uint(f);
    return (u & 0x80000000u) ? ~u : (u | 0x80000000u);
}
__device__ __forceinline__ float decf(unsigned u) {
    return (u & 0x80000000u) ? __uint_as_float(u & 0x7FFFFFFFu)
                             : __uint_as_float(~u);
}

__device__ __forceinline__ uint32_t smem_u32(const void* p) {
    uint32_t a;
    asm("{ .reg .u64 t; cvta.to.shared.u64 t, %1; cvt.u32.u64 %0, t; }" : "=r"(a) : "l"(p));
    return a;
}

// ---- mma / ldmatrix / cp.async ----
__device__ __forceinline__ void mma16816(float* d, const uint32_t* a,
                                         uint32_t b0, uint32_t b1) {
    asm volatile("mma.sync.aligned.m16n8k16.row.col.f32.bf16.bf16.f32 "
        "{%0,%1,%2,%3}, {%4,%5,%6,%7}, {%8,%9}, {%0,%1,%2,%3};"
        : "+f"(d[0]), "+f"(d[1]), "+f"(d[2]), "+f"(d[3])
        : "r"(a[0]), "r"(a[1]), "r"(a[2]), "r"(a[3]), "r"(b0), "r"(b1));
}
#define LDSM_X4(r, a) asm volatile("ldmatrix.sync.aligned.m8n8.x4.shared.b16 {%0,%1,%2,%3}, [%4];" \
    : "=r"((r)[0]),"=r"((r)[1]),"=r"((r)[2]),"=r"((r)[3]) : "r"(a))
#define LDSM_X2(r, a) asm volatile("ldmatrix.sync.aligned.m8n8.x2.shared.b16 {%0,%1}, [%2];" \
    : "=r"((r)[0]),"=r"((r)[1]) : "r"(a))
#define LDSM_X2T(r, a) asm volatile("ldmatrix.sync.aligned.m8n8.x2.trans.shared.b16 {%0,%1}, [%2];" \
    : "=r"((r)[0]),"=r"((r)[1]) : "r"(a))
#define CP_ASYNC16(dst, src) asm volatile("cp.async.cg.shared.global [%0], [%1], 16;" :: "r"(dst), "l"(src))
#define CP_COMMIT() asm volatile("cp.async.commit_group;" ::: "memory")
#define CP_WAIT1() asm volatile("cp.async.wait_group 1;" ::: "memory")
#define CP_WAIT0() asm volatile("cp.async.wait_group 0;" ::: "memory")

__device__ __forceinline__ uint32_t pack2(__nv_bfloat16 x, __nv_bfloat16 y) {
    __nv_bfloat162 v; v.x = x; v.y = y;
    return *(uint32_t*)&v;
}
__device__ __forceinline__ void hilo(float v, __nv_bfloat16& h, __nv_bfloat16& l) {
    h = __float2bfloat16(v);
    l = __float2bfloat16(v - __bfloat162float(h));
}

__global__ void kInit() {
    int i = blockIdx.x*blockDim.x + threadIdx.x;
    if (i < BB*FDC) g_skl[i] = 0u;
}

__global__ void kPrep(const float* __restrict__ memw) {
    int i = blockIdx.x*blockDim.x + threadIdx.x;
    if (i >= FDC*JJ*MMS) return;
    float v = memw[i];
    __nv_bfloat16 h, l; hilo(v, h, l);
    g_mem_hi[i] = h;  g_mem_lo[i] = l;
}

// =====================================================================
// Kernel A: seg+pc projection, HMMA, software-pipelined k-tiles.
//   128 tok x 160 cols, 8 warps (4m x 2n), warp tile 32 x 80, K-tile 32.
// =====================================================================
#define KA_BUF 46080   // bytes per buffer: AsH 10240 + AsL 10240 + WsH 12800 + WsL 12800
__global__ __launch_bounds__(256) void kA(const float* __restrict__ feat,
        const float* __restrict__ seg_w, const float* __restrict__ seg_b,
        const float* __restrict__ pc_w,  const float* __restrict__ pc_b,
        float* __restrict__ out)
{
    extern __shared__ char smA[];
    const uint32_t smb = smem_u32(smA);

    const int tid  = threadIdx.x;
    const int lane = tid & 31;
    const int wid  = tid >> 5;
    const int wm   = wid >> 1, wn = wid & 1;
    const int row0 = wm*32, col0 = wn*80;
    const int t0   = blockIdx.x * 128;

    // ldmatrix per-lane offsets (A: 16-row x4; B: 2-ntile x4), stride 40 bf16 = 80 B
    const uint32_t offA_lm = (uint32_t)(((lane & 7) + ((lane >> 3) & 1)*8)*80 + (lane >> 4)*16);
    const uint32_t offB_lm = (uint32_t)(((lane & 7) + ((lane >> 4) & 1)*8)*80 + ((lane >> 3) & 1)*16);

    float acc[2][10][4];
#pragma unroll
    for (int mt = 0; mt < 2; mt++)
#pragma unroll
        for (int nt = 0; nt < 10; nt++)
#pragma unroll
            for (int r = 0; r < 4; r++) acc[mt][nt][r] = 0.f;

    float4 fA[4], fW[5];

    // ---- tile load (LDG -> regs) ----
    auto ldg_tile = [&](int k0) {
#pragma unroll
        for (int it = 0; it < 4; it++) {
            const int p = tid + it*256, r = p >> 3, c4 = (p & 7)*4;
            fA[it] = *(const float4*)&feat[(size_t)(t0 + r)*DIMC + k0 + c4];
        }
#pragma unroll
        for (int it = 0; it < 5; it++) {
            const int p = tid + it*256, r = p >> 3, c4 = (p & 7)*4;
            float4 v = make_float4(0.f, 0.f, 0.f, 0.f);
            if (r < JJ)            v = *(const float4*)&seg_w[(size_t)r*DIMC + k0 + c4];
            else if (r < JJ + FDC) v = *(const float4*)&pc_w[(size_t)(r - JJ)*DIMC + k0 + c4];
            fW[it] = v;
        }
    };
    // ---- cvt + store regs -> smem buffer ----
    auto sts_tile = [&](int buf) {
        const uint32_t aH = smb + buf*KA_BUF, aL = aH + 10240;
        const uint32_t wH = aH + 20480,       wL = aH + 33280;
#pragma unroll
        for (int it = 0; it < 4; it++) {
            const int p = tid + it*256, r = p >> 3, c4 = (p & 7)*4;
            __nv_bfloat16 h0,l0,h1,l1,h2,l2,h3,l3;
            hilo(fA[it].x,h0,l0); hilo(fA[it].y,h1,l1); hilo(fA[it].z,h2,l2); hilo(fA[it].w,h3,l3);
            *(uint2*)(smA + (aH - smb) + r*80 + c4*2) = uint2{pack2(h0,h1), pack2(h2,h3)};
            *(uint2*)(smA + (aL - smb) + r*80 + c4*2) = uint2{pack2(l0,l1), pack2(l2,l3)};
        }
#pragma unroll
        for (int it = 0; it < 5; it++) {
            const int p = tid + it*256, r = p >> 3, c4 = (p & 7)*4;
            __nv_bfloat16 h0,l0,h1,l1,h2,l2,h3,l3;
            hilo(fW[it].x,h0,l0); hilo(fW[it].y,h1,l1); hilo(fW[it].z,h2,l2); hilo(fW[it].w,h3,l3);
            *(uint2*)(smA + (wH - smb) + r*80 + c4*2) = uint2{pack2(h0,h1), pack2(h2,h3)};
            *(uint2*)(smA + (wL - smb) + r*80 + c4*2) = uint2{pack2(l0,l1), pack2(l2,l3)};
        }
    };

    ldg_tile(0);
    sts_tile(0);
    __syncthreads();

    for (int it = 0; it < 32; it++) {
        const int buf = it & 1;
        if (it < 31) ldg_tile((it + 1)*32);

        const uint32_t aH = smb + buf*KA_BUF, aL = aH + 10240;
        const uint32_t wH = aH + 20480,       wL = aH + 33280;
#pragma unroll
        for (int ks = 0; ks < 2; ks++) {
            const uint32_t kkB = ks*32;
            uint32_t ah0[4], ah1[4], al0[4], al1[4];
            LDSM_X4(ah0, aH + offA_lm + row0*80 + kkB);
            LDSM_X4(ah1, aH + offA_lm + (row0 + 16)*80 + kkB);
            LDSM_X4(al0, aL + offA_lm + row0*80 + kkB);
            LDSM_X4(al1, aL + offA_lm + (row0 + 16)*80 + kkB);
#pragma unroll
            for (int ntp = 0; ntp < 5; ntp++) {
                const uint32_t nOff = (col0 + ntp*16)*80;
                uint32_t bh[4], bl[4];
                LDSM_X4(bh, wH + offB_lm + nOff + kkB);
                LDSM_X4(bl, wL + offB_lm + nOff + kkB);
                // nt = 2*ntp (regs bh[0],bh[1]) and 2*ntp+1 (bh[2],bh[3])
                mma16816(acc[0][2*ntp],   ah0, bh[0], bh[1]);
                mma16816(acc[0][2*ntp],   ah0, bl[0], bl[1]);
                mma16816(acc[0][2*ntp],   al0, bh[0], bh[1]);
                mma16816(acc[1][2*ntp],   ah1, bh[0], bh[1]);
                mma16816(acc[1][2*ntp],   ah1, bl[0], bl[1]);
                mma16816(acc[1][2*ntp],   al1, bh[0], bh[1]);
                mma16816(acc[0][2*ntp+1], ah0, bh[2], bh[3]);
                mma16816(acc[0][2*ntp+1], ah0, bl[2], bl[3]);
                mma16816(acc[0][2*ntp+1], al0, bh[2], bh[3]);
                mma16816(acc[1][2*ntp+1], ah1, bh[2], bh[3]);
                mma16816(acc[1][2*ntp+1], ah1, bl[2], bl[3]);
                mma16816(acc[1][2*ntp+1], al1, bh[2], bh[3]);
            }
        }
        if (it < 31) sts_tile(buf ^ 1);
        __syncthreads();
    }

    const int lq = lane >> 2, lr = lane & 3;
    // ---- pc epilogue ----
#pragma unroll
    for (int mt = 0; mt < 2; mt++)
#pragma unroll
        for (int nt = 0; nt < 10; nt++) {
            const int c0 = col0 + nt*8 + lr*2;
            if (c0 < 24 || c0 >= 152) continue;
            const int d = c0 - 24;
#pragma unroll
            for (int half = 0; half < 2; half++) {
                const int token = t0 + row0 + mt*16 + lq + half*8;
                const float v0 = acc[mt][nt][half*2 + 0] + pc_b[d];
                const float v1 = acc[mt][nt][half*2 + 1] + pc_b[d + 1];
                __nv_bfloat16 h0,l0,h1,l1;
                hilo(v0,h0,l0); hilo(v1,h1,l1);
                *(__nv_bfloat162*)&g_pc_hi[(size_t)token*FDC + d] = __nv_bfloat162{h0,h1};
                *(__nv_bfloat162*)&g_pc_lo[(size_t)token*FDC + d] = __nv_bfloat162{l0,l1};
            }
        }
    // ---- seg epilogue (wn==0, n-tiles 0..2) ----
    if (wn == 0) {
#pragma unroll
        for (int mt = 0; mt < 2; mt++)
#pragma unroll
            for (int half = 0; half < 2; half++) {
                const int row = row0 + mt*16 + lq + half*8;
                float v[6];
#pragma unroll
                for (int nt = 0; nt < 3; nt++)
#pragma unroll
                    for (int q = 0; q < 2; q++)
                        v[nt*2 + q] = acc[mt][nt][half*2 + q] + seg_b[nt*8 + lr*2 + q];
                float mx = v[0];
#pragma unroll
                for (int q = 1; q < 6; q++) mx = fmaxf(mx, v[q]);
                mx = fmaxf(mx, __shfl_xor_sync(0xffffffffu, mx, 1));
                mx = fmaxf(mx, __shfl_xor_sync(0xffffffffu, mx, 2));
                float s = 0.f;
#pragma unroll
                for (int q = 0; q < 6; q++) { v[q] = expf(v[q] - mx); s += v[q]; }
                s += __shfl_xor_sync(0xffffffffu, s, 1);
                s += __shfl_xor_sync(0xffffffffu, s, 2);
                const float inv = 1.f / s;
                const int t = t0 + row;
                const int b = t / NT; const int rr = t % NT;
                const int l = rr / NNP; const int nn = rr % NNP;
                float* segout = out + SEG_OFF + ((size_t)(b*LL + l)*JJ)*NNP + nn;
#pragma unroll
                for (int nt = 0; nt < 3; nt++)
#pragma unroll
                    for (int q = 0; q < 2; q++)
                        segout[(size_t)(nt*8 + lr*2 + q)*NNP] = v[nt*2 + q]*inv;
            }
    }
}

// =====================================================================
// Kernel B: forward_mem, HMMA, attn-in-registers, double-buffered mem tile
// =====================================================================
#define OFF_A1H  0          // 128 x 136 bf16 = 34816
#define OFF_A1L  34816
#define OFF_B2H0 69632      // 128 x 72 bf16 = 18432 (x2 bufs)
#define OFF_B2L0 106496     // (x2 bufs)
#define OFF_SEG  143360     // 128*25 floats = 12800
#define OFF_DMAX 156160     // 128 unsigned
#define OFF_WSUM 156672     // 8 floats
#define SMEM_B_TOTAL 156704

__global__ __launch_bounds__(256) void kB(const float* __restrict__ segp)
{
    extern __shared__ char sm[];
    const uint32_t smb = smem_u32(sm);
    __nv_bfloat16* A1H = (__nv_bfloat16*)(sm + OFF_A1H);
    __nv_bfloat16* A1L = (__nv_bfloat16*)(sm + OFF_A1L);
    float*    segS = (float*)(sm + OFF_SEG);
    unsigned* dmax = (unsigned*)(sm + OFF_DMAX);
    float*    wsum = (float*)(sm + OFF_WSUM);

    const int tid  = threadIdx.x;
    const int lane = tid & 31;
    const int wid  = tid >> 5;
    const int row0 = wid*16;
    const int g    = lane >> 2, t = lane & 3;
    const int lane16 = lane & 15;
    const int b   = blockIdx.x / (NT/TBB);
    const int n0  = (blockIdx.x % (NT/TBB)) * TBB;

    // per-lane ldmatrix offset pieces
    const uint32_t offA1_lm = (uint32_t)((row0 + (lane & 7) + ((lane >> 3) & 1)*8)*272 + (lane >> 4)*16);
    const uint32_t offB1t   = (uint32_t)(((lane16 & 7) + (lane16 >> 3)*8)*144);            // trans: rows = d
    const uint32_t offB2n   = (uint32_t)((lane16 & 7)*144 + (lane16 >> 3)*16);             // plain: rows = d

    // prefetch chunk 0 mem tile
    auto prefetch = [&](int chn, int bufn) {
        const int k0 = chn*MMS;
        const uint32_t dH = smb + OFF_B2H0 + bufn*18432;
        const uint32_t dL = smb + OFF_B2L0 + bufn*18432;
#pragma unroll
        for (int it = 0; it < 4; it++) {
            const int p = tid + it*256, d = p >> 3, j = p & 7;
            CP_ASYNC16(dH + d*144 + j*16, (const char*)g_mem_hi + ((size_t)d*(JJ*MMS) + k0)*2 + j*16);
            CP_ASYNC16(dL + d*144 + j*16, (const char*)g_mem_lo + ((size_t)d*(JJ*MMS) + k0)*2 + j*16);
        }
    };
    prefetch(0, 0); CP_COMMIT();

    // A1: pc tile hi/lo
    {
        const size_t base = ((size_t)b*NT + n0)*FDC;
#pragma unroll
        for (int it = 0; it < 16; it++) {
            const int p = tid + it*256;              // 0..4095 (4B-pairs x2 arrays)
            const int r = p >> 5, c4 = (p & 31)*4;
            *(uint2*)&A1H[r*136 + c4] = *(const uint2*)&g_pc_hi[base + (size_t)r*FDC + c4];
            *(uint2*)&A1L[r*136 + c4] = *(const uint2*)&g_pc_lo[base + (size_t)r*FDC + c4];
        }
    }
    // seg tile [tok][25]
    {
        const int l = n0 / NNP, nn0 = n0 % NNP;
        const float* sp = segp + ((size_t)(b*LL + l)*JJ)*NNP + nn0;
        for (int idx = tid; idx < TBB*JJ; idx += 256) {
            const int j = idx >> 7, m = idx & 127;
            segS[m*25 + j] = sp[(size_t)j*NNP + m];
        }
    }
    if (tid < FDC) dmax[tid] = 0u;

    float racc[16][4];
#pragma unroll
    for (int nt = 0; nt < 16; nt++)
#pragma unroll
        for (int r = 0; r < 4; r++) racc[nt][r] = 0.f;
    float psum0 = 0.f, psum1 = 0.f;
    const float invs = 0.088388347648318447f;

    for (int ch = 0; ch < JJ; ++ch) {
        __syncthreads();                 // everyone done reading buf[(ch+1)&1]
        if (ch < JJ - 1) { prefetch(ch + 1, (ch + 1) & 1); CP_COMMIT(); CP_WAIT1(); }
        else CP_WAIT0();
        __syncthreads();                 // buf[ch&1] visible to all

        const int buf = ch & 1;
        const uint32_t b2h = smb + OFF_B2H0 + buf*18432;
        const uint32_t b2l = smb + OFF_B2L0 + buf*18432;

        // ---- MMA1: logits[16 tok x 64 slots], K = 128 dims ----
        float lacc[8][4];
#pragma unroll
        for (int nt = 0; nt < 8; nt++)
#pragma unroll
            for (int r = 0; r < 4; r++) lacc[nt][r] = 0.f;
#pragma unroll
        for (int ks = 0; ks < 8; ks++) {
            uint32_t ah[4], al[4];
            LDSM_X4(ah, smb + OFF_A1H + offA1_lm + ks*32);
            LDSM_X4(al, smb + OFF_A1L + offA1_lm + ks*32);
#pragma unroll
            for (int nt = 0; nt < 8; nt++) {
                uint32_t bh[2], bl[2];
                LDSM_X2T(bh, b2h + offB1t + ks*2304 + nt*16);
                LDSM_X2T(bl, b2l + offB1t + ks*2304 + nt*16);
                mma16816(lacc[nt], ah, bh[0], bh[1]);
                mma16816(lacc[nt], ah, bl[0], bl[1]);
                mma16816(lacc[nt], al, bh[0], bh[1]);
            }
        }

        // ---- exp + pack attn A-fragments in registers ----
        const float sv0 = segS[(row0 + g)*25 + ch] * invs;
        const float sv1 = segS[(row0 + g + 8)*25 + ch] * invs;
        uint32_t aHf[4][4], aLf[4][4];
#pragma unroll
        for (int nt = 0; nt < 8; nt++) {
            const float p0 = __expf(lacc[nt][0]*sv0);
            const float p1 = __expf(lacc[nt][1]*sv0);
            const float p2 = __expf(lacc[nt][2]*sv1);
            const float p3 = __expf(lacc[nt][3]*sv1);
            psum0 += p0 + p1;  psum1 += p2 + p3;
            __nv_bfloat16 h0,l0,h1,l1,h2,l2,h3,l3;
            hilo(p0,h0,l0); hilo(p1,h1,l1); hilo(p2,h2,l2); hilo(p3,h3,l3);
            const int ks2 = nt >> 1, hf = nt & 1;
            aHf[ks2][hf*2 + 0] = pack2(h0, h1);
            aHf[ks2][hf*2 + 1] = pack2(h2, h3);
            aLf[ks2][hf*2 + 0] = pack2(l0, l1);
            aLf[ks2][hf*2 + 1] = pack2(l2, l3);
        }

        // ---- MMA2: rec[16 tok x 128 dims] += attn @ mem, K = 64 slots ----
#pragma unroll
        for (int ks2 = 0; ks2 < 4; ks2++) {
#pragma unroll
            for (int nt2 = 0; nt2 < 16; nt2++) {
                uint32_t bh[2], bl[2];
                LDSM_X2(bh, b2h + offB2n + nt2*1152 + ks2*32);
                LDSM_X2(bl, b2l + offB2n + nt2*1152 + ks2*32);
                mma16816(racc[nt2], aHf[ks2], bh[0], bh[1]);
                mma16816(racc[nt2], aHf[ks2], bl[0], bl[1]);
                mma16816(racc[nt2], aLf[ks2], bh[0], bh[1]);
            }
        }
    }

    // psum: quad-reduce over t lanes (bits 0,1)
    psum0 += __shfl_xor_sync(0xffffffffu, psum0, 1);
    psum0 += __shfl_xor_sync(0xffffffffu, psum0, 2);
    psum1 += __shfl_xor_sync(0xffffffffu, psum1, 1);
    psum1 += __shfl_xor_sync(0xffffffffu, psum1, 2);
    const float inv0 = 1.f / psum0, inv1 = 1.f / psum1;

    // epilogue: normalize, loss, per-dim max
    float lossloc = 0.f;
    const int r0g = row0 + g, r1g = row0 + g + 8;
#pragma unroll
    for (int nt2 = 0; nt2 < 16; nt2++) {
        const int c = nt2*8 + t*2;
        const float rec00 = racc[nt2][0]*inv0, rec01 = racc[nt2][1]*inv0;
        const float rec10 = racc[nt2][2]*inv1, rec11 = racc[nt2][3]*inv1;
        const __nv_bfloat162 ph0 = *(const __nv_bfloat162*)&A1H[r0g*136 + c];
        const __nv_bfloat162 pl0 = *(const __nv_bfloat162*)&A1L[r0g*136 + c];
        const __nv_bfloat162 ph1 = *(const __nv_bfloat162*)&A1H[r1g*136 + c];
        const __nv_bfloat162 pl1 = *(const __nv_bfloat162*)&A1L[r1g*136 + c];
        float d0 = rec00 - (__bfloat162float(ph0.x) + __bfloat162float(pl0.x));
        float d1 = rec01 - (__bfloat162float(ph0.y) + __bfloat162float(pl0.y));
        float d2 = rec10 - (__bfloat162float(ph1.x) + __bfloat162float(pl1.x));
        float d3 = rec11 - (__bfloat162float(ph1.y) + __bfloat162float(pl1.y));
        lossloc += d0*d0 + d1*d1 + d2*d2 + d3*d3;
        atomicMax(&dmax[c],     encf(fmaxf(rec00, rec10)));
        atomicMax(&dmax[c + 1], encf(fmaxf(rec01, rec11)));
    }
    __syncthreads();
    if (tid < FDC) atomicMax(&g_skl[b*FDC + tid], dmax[tid]);
#pragma unroll
    for (int o = 16; o > 0; o >>= 1)
        lossloc += __shfl_xor_sync(0xffffffffu, lossloc, o);
    if (lane == 0) wsum[wid] = lossloc;
    __syncthreads();
    if (tid == 0) {
        float s = 0.f;
        for (int w = 0; w < 8; w++) s += wsum[w];
        g_lossPartial[blockIdx.x] = s;
    }
}

// =====================================================================
// Kernel C: 4 blocks (one per batch); block 0 also finalizes loss
// =====================================================================
__global__ __launch_bounds__(256) void kC(const float* __restrict__ ln_g,
        const float* __restrict__ ln_b, const float* __restrict__ w1,
        const float* __restrict__ b1,   const float* __restrict__ w2,
        const float* __restrict__ b2,   float* __restrict__ out)
{
    __shared__ float red[128];
    __shared__ float hbuf[128];
    __shared__ float h2[64];
    __shared__ float wsum2[8];
    const int tid = threadIdx.x;
    const int b   = blockIdx.x;

    if (b == 0) {
        float s = 0.f;
        for (int i = tid; i < NBLK_B; i += 256) s += g_lossPartial[i];
#pragma unroll
        for (int o = 16; o > 0; o >>= 1) s += __shfl_xor_sync(0xffffffffu, s, o);
        if ((tid & 31) == 0) wsum2[tid >> 5] = s;
        __syncthreads();
        if (tid == 0) {
            float tt = 0.f;
            for (int w = 0; w < 8; w++) tt += wsum2[w];
            out[LOSS_OFF] = tt / ((float)TOK * (float)FDC);
        }
    }

    float x = 0.f;
    if (tid < FDC) { x = decf(g_skl[b*FDC + tid]); red[tid] = x; }
    __syncthreads();
    for (int o = 64; o > 0; o >>= 1) {
        if (tid < o) red[tid] += red[tid + o];
        __syncthreads();
    }
    const float mu = red[0] * (1.f/FDC);
    __syncthreads();
    const float dfx = x - mu;
    if (tid < FDC) red[tid] = dfx*dfx;
    __syncthreads();
    for (int o = 64; o > 0; o >>= 1) {
        if (tid < o) red[tid] += red[tid + o];
        __syncthreads();
    }
    const float var = red[0] * (1.f/FDC);
    __syncthreads();
    if (tid < FDC)
        hbuf[tid] = dfx * rsqrtf(var + 1e-5f) * ln_g[tid] + ln_b[tid];
    __syncthreads();
    if (tid < FDC/2) {
        float a = b1[tid];
        for (int d = 0; d < FDC; ++d) a = fmaf(hbuf[d], w1[tid*FDC + d], a);
        h2[tid] = 0.5f * a * (1.f + erff(a * 0.70710678118654752f));
    }
    __syncthreads();
    if (tid < OUTC) {
        float a = b2[tid];
        for (int e = 0; e < FDC/2; ++e) a = fmaf(h2[e], w2[tid*(FDC/2) + e], a);
        out[b*OUTC + tid] = a;
    }
}

extern "C" void kernel_launch(void* const* d_in, const int* in_sizes, int n_in,
                              void* d_out, int out_size)
{
    const float* feat  = (const float*)d_in[0];
    const float* seg_w = (const float*)d_in[1];
    const float* seg_b = (const float*)d_in[2];
    const float* pc_w  = (const float*)d_in[3];
    const float* pc_b  = (const float*)d_in[4];
    const float* memw  = (const float*)d_in[5];
    const float* ln_g  = (const float*)d_in[6];
    const float* ln_b  = (const float*)d_in[7];
    const float* w1    = (const float*)d_in[8];
    const float* b1    = (const float*)d_in[9];
    const float* w2    = (const float*)d_in[10];
    const float* b2    = (const float*)d_in[11];
    float* out = (float*)d_out;

    cudaFuncSetAttribute(kA, cudaFuncAttributeMaxDynamicSharedMemorySize, 2*KA_BUF);
    cudaFuncSetAttribute(kB, cudaFuncAttributeMaxDynamicSharedMemorySize, SMEM_B_TOTAL);

    kInit<<<1, 512>>>();
    kPrep<<<(FDC*JJ*MMS + 255)/256, 256>>>(memw);
    kA<<<TOK/128, 256, 2*KA_BUF>>>(feat, seg_w, seg_b, pc_w, pc_b, out);
    kB<<<NBLK_B, 256, SMEM_B_TOTAL>>>(out + SEG_OFF);
    kC<<<4, 256>>>(ln_g, ln_b, w1, b1, w2, b2, out);
}

// round 5
// speedup vs baseline: 3.7406x; 1.1471x over previous
#include <cuda_runtime.h>
#include <cuda_bf16.h>
#include <math.h>
#include <cstdint>

// ---- problem dims ----
#define BB   4
#define LL   24
#define NNP  512
#define DIMC 1024
#define JJ   24
#define MMS  64
#define FDC  128
#define OUTC 72
#define NT   (LL*NNP)
#define TOK  (BB*NT)

#define SEG_OFF  (BB*OUTC)
#define SEG_SIZE (BB*LL*JJ*NNP)
#define LOSS_OFF (SEG_OFF + SEG_SIZE)

#define TBB 128
#define NBLK_B (BB*(NT/TBB))           // 384

// ---- device scratch ----
__device__ __nv_bfloat16 g_pc_hi[(size_t)TOK*FDC];
__device__ __nv_bfloat16 g_pc_lo[(size_t)TOK*FDC];
__device__ __nv_bfloat16 g_mem_hi[FDC*JJ*MMS];    // [d][slot]
__device__ __nv_bfloat16 g_mem_lo[FDC*JJ*MMS];
__device__ __nv_bfloat16 g_w_hi[32*160*32];       // [ktile][row][k-in-tile]
__device__ __nv_bfloat16 g_w_lo[32*160*32];
__device__ float    g_lossPartial[NBLK_B];
__device__ unsigned g_skl[BB*FDC];

__device__ __forceinline__ unsigned encf(float f) {
    unsigned u = __float_as_uint(f);
    return (u & 0x80000000u) ? ~u : (u | 0x80000000u);
}
__device__ __forceinline__ float decf(unsigned u) {
    return (u & 0x80000000u) ? __uint_as_float(u & 0x7FFFFFFFu)
                             : __uint_as_float(~u);
}

__device__ __forceinline__ uint32_t smem_u32(const void* p) {
    uint32_t a;
    asm("{ .reg .u64 t; cvta.to.shared.u64 t, %1; cvt.u32.u64 %0, t; }" : "=r"(a) : "l"(p));
    return a;
}

// ---- mma / ldmatrix / cp.async ----
__device__ __forceinline__ void mma16816(float* d, const uint32_t* a,
                                         uint32_t b0, uint32_t b1) {
    asm volatile("mma.sync.aligned.m16n8k16.row.col.f32.bf16.bf16.f32 "
        "{%0,%1,%2,%3}, {%4,%5,%6,%7}, {%8,%9}, {%0,%1,%2,%3};"
        : "+f"(d[0]), "+f"(d[1]), "+f"(d[2]), "+f"(d[3])
        : "r"(a[0]), "r"(a[1]), "r"(a[2]), "r"(a[3]), "r"(b0), "r"(b1));
}
#define LDSM_X4(r, a) asm volatile("ldmatrix.sync.aligned.m8n8.x4.shared.b16 {%0,%1,%2,%3}, [%4];" \
    : "=r"((r)[0]),"=r"((r)[1]),"=r"((r)[2]),"=r"((r)[3]) : "r"(a))
#define LDSM_X4T(r, a) asm volatile("ldmatrix.sync.aligned.m8n8.x4.trans.shared.b16 {%0,%1,%2,%3}, [%4];" \
    : "=r"((r)[0]),"=r"((r)[1]),"=r"((r)[2]),"=r"((r)[3]) : "r"(a))
#define CP_ASYNC16(dst, src) asm volatile("cp.async.cg.shared.global [%0], [%1], 16;" :: "r"(dst), "l"(src))
#define CP_COMMIT() asm volatile("cp.async.commit_group;" ::: "memory")
#define CP_WAIT1() asm volatile("cp.async.wait_group 1;" ::: "memory")
#define CP_WAIT0() asm volatile("cp.async.wait_group 0;" ::: "memory")

__device__ __forceinline__ uint32_t pack2(__nv_bfloat16 x, __nv_bfloat16 y) {
    __nv_bfloat162 v; v.x = x; v.y = y;
    return *(uint32_t*)&v;
}
__device__ __forceinline__ void hilo(float v, __nv_bfloat16& h, __nv_bfloat16& l) {
    h = __float2bfloat16(v);
    l = __float2bfloat16(v - __bfloat162float(h));
}

__global__ void kInit() {
    int i = blockIdx.x*blockDim.x + threadIdx.x;
    if (i < BB*FDC) g_skl[i] = 0u;
}

__global__ void kPrep(const float* __restrict__ memw) {
    int i = blockIdx.x*blockDim.x + threadIdx.x;
    if (i >= FDC*JJ*MMS) return;
    float v = memw[i];
    __nv_bfloat16 h, l; hilo(v, h, l);
    g_mem_hi[i] = h;  g_mem_lo[i] = l;
}

__global__ void kPrepW(const float* __restrict__ seg_w, const float* __restrict__ pc_w) {
    int i = blockIdx.x*blockDim.x + threadIdx.x;
    if (i >= 32*160*32) return;
    const int kk = i & 31, row = (i >> 5) % 160, kt = i / (160*32);
    float v = 0.f;
    if (row < JJ)            v = seg_w[row*DIMC + kt*32 + kk];
    else if (row < JJ + FDC) v = pc_w[(row - JJ)*DIMC + kt*32 + kk];
    __nv_bfloat16 h, l; hilo(v, h, l);
    g_w_hi[i] = h;  g_w_lo[i] = l;
}

// =====================================================================
// Kernel A: seg+pc projection, HMMA, pipelined k-tiles.
//   feat: LDG->regs->cvt->smem; W: pre-converted, cp.async.
// =====================================================================
#define KA_BUF 46080   // AsH 10240 + AsL 10240 + WsH 12800 + WsL 12800
__global__ __launch_bounds__(256) void kA(const float* __restrict__ feat,
        const float* __restrict__ seg_b, const float* __restrict__ pc_b,
        float* __restrict__ out)
{
    extern __shared__ char smA[];
    const uint32_t smb = smem_u32(smA);

    const int tid  = threadIdx.x;
    const int lane = tid & 31;
    const int wid  = tid >> 5;
    const int wm   = wid >> 1, wn = wid & 1;
    const int row0 = wm*32, col0 = wn*80;
    const int t0   = blockIdx.x * 128;

    const uint32_t offA_lm = (uint32_t)(((lane & 7) + ((lane >> 3) & 1)*8)*80 + (lane >> 4)*16);
    const uint32_t offB_lm = (uint32_t)(((lane & 7) + ((lane >> 4) & 1)*8)*80 + ((lane >> 3) & 1)*16);

    float acc[2][10][4];
#pragma unroll
    for (int mt = 0; mt < 2; mt++)
#pragma unroll
        for (int nt = 0; nt < 10; nt++)
#pragma unroll
            for (int r = 0; r < 4; r++) acc[mt][nt][r] = 0.f;

    float4 fA[4];

    auto ldg_tile = [&](int k0) {
#pragma unroll
        for (int it = 0; it < 4; it++) {
            const int p = tid + it*256, r = p >> 3, c4 = (p & 7)*4;
            fA[it] = *(const float4*)&feat[(size_t)(t0 + r)*DIMC + k0 + c4];
        }
    };
    auto sts_tile = [&](int buf) {
        const uint32_t aH = buf*KA_BUF, aL = aH + 10240;
#pragma unroll
        for (int it = 0; it < 4; it++) {
            const int p = tid + it*256, r = p >> 3, c4 = (p & 7)*4;
            __nv_bfloat16 h0,l0,h1,l1,h2,l2,h3,l3;
            hilo(fA[it].x,h0,l0); hilo(fA[it].y,h1,l1); hilo(fA[it].z,h2,l2); hilo(fA[it].w,h3,l3);
            *(uint2*)(smA + aH + r*80 + c4*2) = uint2{pack2(h0,h1), pack2(h2,h3)};
            *(uint2*)(smA + aL + r*80 + c4*2) = uint2{pack2(l0,l1), pack2(l2,l3)};
        }
    };
    auto cpW = [&](int kt, int buf) {
        const uint32_t wH = smb + buf*KA_BUF + 20480;
        const uint32_t wL = wH + 12800;
#pragma unroll
        for (int it2 = 0; it2 < 5; it2++) {
            const int p = tid + it2*256;           // 0..1279
            const int arr = p / 640, q = p - arr*640;
            const int r = q >> 2, c = q & 3;
            const uint32_t dst = (arr ? wL : wH) + r*80 + c*16;
            const char* src = (const char*)(arr ? g_w_lo : g_w_hi)
                            + ((size_t)(kt*160 + r)*32 + c*8)*2;
            CP_ASYNC16(dst, src);
        }
    };

    cpW(0, 0); CP_COMMIT();
    ldg_tile(0);
    sts_tile(0);
    CP_WAIT0();
    __syncthreads();

    for (int it = 0; it < 32; it++) {
        const int buf = it & 1;
        if (it < 31) { ldg_tile((it + 1)*32); cpW(it + 1, buf ^ 1); CP_COMMIT(); }

        const uint32_t aH = smb + buf*KA_BUF, aL = aH + 10240;
        const uint32_t wH = aH + 20480,       wL = aH + 33280;
#pragma unroll
        for (int ks = 0; ks < 2; ks++) {
            const uint32_t kkB = ks*32;
            uint32_t ah0[4], ah1[4], al0[4], al1[4];
            LDSM_X4(ah0, aH + offA_lm + row0*80 + kkB);
            LDSM_X4(ah1, aH + offA_lm + (row0 + 16)*80 + kkB);
            LDSM_X4(al0, aL + offA_lm + row0*80 + kkB);
            LDSM_X4(al1, aL + offA_lm + (row0 + 16)*80 + kkB);
#pragma unroll
            for (int ntp = 0; ntp < 5; ntp++) {
                const uint32_t nOff = (col0 + ntp*16)*80;
                uint32_t bh[4], bl[4];
                LDSM_X4(bh, wH + offB_lm + nOff + kkB);
                LDSM_X4(bl, wL + offB_lm + nOff + kkB);
                mma16816(acc[0][2*ntp],   ah0, bh[0], bh[1]);
                mma16816(acc[0][2*ntp],   ah0, bl[0], bl[1]);
                mma16816(acc[0][2*ntp],   al0, bh[0], bh[1]);
                mma16816(acc[1][2*ntp],   ah1, bh[0], bh[1]);
                mma16816(acc[1][2*ntp],   ah1, bl[0], bl[1]);
                mma16816(acc[1][2*ntp],   al1, bh[0], bh[1]);
                mma16816(acc[0][2*ntp+1], ah0, bh[2], bh[3]);
                mma16816(acc[0][2*ntp+1], ah0, bl[2], bl[3]);
                mma16816(acc[0][2*ntp+1], al0, bh[2], bh[3]);
                mma16816(acc[1][2*ntp+1], ah1, bh[2], bh[3]);
                mma16816(acc[1][2*ntp+1], ah1, bl[2], bl[3]);
                mma16816(acc[1][2*ntp+1], al1, bh[2], bh[3]);
            }
        }
        if (it < 31) sts_tile(buf ^ 1);
        CP_WAIT0();
        __syncthreads();
    }

    const int lq = lane >> 2, lr = lane & 3;
    // ---- pc epilogue ----
#pragma unroll
    for (int mt = 0; mt < 2; mt++)
#pragma unroll
        for (int nt = 0; nt < 10; nt++) {
            const int c0 = col0 + nt*8 + lr*2;
            if (c0 < 24 || c0 >= 152) continue;
            const int d = c0 - 24;
#pragma unroll
            for (int half = 0; half < 2; half++) {
                const int token = t0 + row0 + mt*16 + lq + half*8;
                const float v0 = acc[mt][nt][half*2 + 0] + pc_b[d];
                const float v1 = acc[mt][nt][half*2 + 1] + pc_b[d + 1];
                __nv_bfloat16 h0,l0,h1,l1;
                hilo(v0,h0,l0); hilo(v1,h1,l1);
                *(__nv_bfloat162*)&g_pc_hi[(size_t)token*FDC + d] = __nv_bfloat162{h0,h1};
                *(__nv_bfloat162*)&g_pc_lo[(size_t)token*FDC + d] = __nv_bfloat162{l0,l1};
            }
        }
    // ---- seg epilogue (wn==0, n-tiles 0..2) ----
    if (wn == 0) {
#pragma unroll
        for (int mt = 0; mt < 2; mt++)
#pragma unroll
            for (int half = 0; half < 2; half++) {
                const int row = row0 + mt*16 + lq + half*8;
                float v[6];
#pragma unroll
                for (int nt = 0; nt < 3; nt++)
#pragma unroll
                    for (int q = 0; q < 2; q++)
                        v[nt*2 + q] = acc[mt][nt][half*2 + q] + seg_b[nt*8 + lr*2 + q];
                float mx = v[0];
#pragma unroll
                for (int q = 1; q < 6; q++) mx = fmaxf(mx, v[q]);
                mx = fmaxf(mx, __shfl_xor_sync(0xffffffffu, mx, 1));
                mx = fmaxf(mx, __shfl_xor_sync(0xffffffffu, mx, 2));
                float s = 0.f;
#pragma unroll
                for (int q = 0; q < 6; q++) { v[q] = expf(v[q] - mx); s += v[q]; }
                s += __shfl_xor_sync(0xffffffffu, s, 1);
                s += __shfl_xor_sync(0xffffffffu, s, 2);
                const float inv = 1.f / s;
                const int t = t0 + row;
                const int b = t / NT; const int rr = t % NT;
                const int l = rr / NNP; const int nn = rr % NNP;
                float* segout = out + SEG_OFF + ((size_t)(b*LL + l)*JJ)*NNP + nn;
#pragma unroll
                for (int nt = 0; nt < 3; nt++)
#pragma unroll
                    for (int q = 0; q < 2; q++)
                        segout[(size_t)(nt*8 + lr*2 + q)*NNP] = v[nt*2 + q]*inv;
            }
    }
}

// =====================================================================
// Kernel B: forward_mem, HMMA, 512 threads: warp pairs split the 64-slot
// chunk (h = slot half). attn stays in registers; rec partials combined
// once at the end through smem.
// =====================================================================
#define OFF_A1H  0          // 128 x 136 bf16 = 34816
#define OFF_A1L  34816
#define OFF_B2H0 69632      // 128 x 72 bf16 = 18432 (x2 bufs)
#define OFF_B2L0 106496     // (x2 bufs)
#define OFF_SEG  143360     // 128*25 floats
#define OFF_PSUM 156160     // 128 floats
#define OFF_DMAX 156672     // 128 unsigned
#define OFF_WSUM 157184     // 16 floats
#define SMEM_B_TOTAL 157248

__global__ __launch_bounds__(512, 1) void kB(const float* __restrict__ segp)
{
    extern __shared__ char sm[];
    const uint32_t smb = smem_u32(sm);
    __nv_bfloat16* A1H = (__nv_bfloat16*)(sm + OFF_A1H);
    __nv_bfloat16* A1L = (__nv_bfloat16*)(sm + OFF_A1L);
    float*    segS  = (float*)(sm + OFF_SEG);
    float*    psumP = (float*)(sm + OFF_PSUM);
    unsigned* dmax  = (unsigned*)(sm + OFF_DMAX);
    float*    wsum  = (float*)(sm + OFF_WSUM);

    const int tid  = threadIdx.x;
    const int lane = tid & 31;
    const int wid  = tid >> 5;          // 0..15
    const int wm   = wid & 7;           // token-row group
    const int h    = wid >> 3;          // slot half: 0 -> 0..31, 1 -> 32..63
    const int row0 = wm*16;
    const int g    = lane >> 2, t = lane & 3;
    const int b   = blockIdx.x / (NT/TBB);
    const int n0  = (blockIdx.x % (NT/TBB)) * TBB;

    const uint32_t offA1_lm = (uint32_t)((row0 + (lane & 7) + ((lane >> 3) & 1)*8)*272 + (lane >> 4)*16);
    // trans B (logits): matrices {k0-7,n0-7},{k8-15,n0-7},{k0-7,n8-15},{k8-15,n8-15}
    const uint32_t offB1t4 = (uint32_t)(((lane & 7) + ((lane >> 3) & 1)*8)*144 + (lane >> 4)*16);
    // plain B (rec): matrices {n0-7,k0-7},{n0-7,k8-15},{n8-15,k0-7},{n8-15,k8-15}
    const uint32_t offB2n4 = (uint32_t)((lane & 7)*144 + ((lane >> 3) & 1)*16 + (lane >> 4)*1152);

    auto prefetch = [&](int chn, int bufn) {
        const int k0 = chn*MMS;
        const uint32_t dH = smb + OFF_B2H0 + bufn*18432;
        const uint32_t dL = smb + OFF_B2L0 + bufn*18432;
#pragma unroll
        for (int it = 0; it < 2; it++) {
            const int p = tid + it*512, d = p >> 3, j = p & 7;
            CP_ASYNC16(dH + d*144 + j*16, (const char*)g_mem_hi + ((size_t)d*(JJ*MMS) + k0)*2 + j*16);
            CP_ASYNC16(dL + d*144 + j*16, (const char*)g_mem_lo + ((size_t)d*(JJ*MMS) + k0)*2 + j*16);
        }
    };
    prefetch(0, 0); CP_COMMIT();

    // A1: pc tile hi/lo
    {
        const size_t base = ((size_t)b*NT + n0)*FDC;
#pragma unroll
        for (int it = 0; it < 8; it++) {
            const int p = tid + it*512;
            const int r = p >> 5, c4 = (p & 31)*4;
            *(uint2*)&A1H[r*136 + c4] = *(const uint2*)&g_pc_hi[base + (size_t)r*FDC + c4];
            *(uint2*)&A1L[r*136 + c4] = *(const uint2*)&g_pc_lo[base + (size_t)r*FDC + c4];
        }
    }
    // seg tile [tok][25]
    {
        const int l = n0 / NNP, nn0 = n0 % NNP;
        const float* sp = segp + ((size_t)(b*LL + l)*JJ)*NNP + nn0;
        for (int idx = tid; idx < TBB*JJ; idx += 512) {
            const int j = idx >> 7, m = idx & 127;
            segS[m*25 + j] = sp[(size_t)j*NNP + m];
        }
    }
    if (tid < FDC) dmax[tid] = 0u;

    float racc[16][4];
#pragma unroll
    for (int nt = 0; nt < 16; nt++)
#pragma unroll
        for (int r = 0; r < 4; r++) racc[nt][r] = 0.f;
    float psum0 = 0.f, psum1 = 0.f;
    const float invs = 0.088388347648318447f;

    for (int ch = 0; ch < JJ; ++ch) {
        __syncthreads();
        if (ch < JJ - 1) { prefetch(ch + 1, (ch + 1) & 1); CP_COMMIT(); CP_WAIT1(); }
        else CP_WAIT0();
        __syncthreads();

        const int buf = ch & 1;
        const uint32_t b2h = smb + OFF_B2H0 + buf*18432;
        const uint32_t b2l = smb + OFF_B2L0 + buf*18432;

        // ---- MMA1: logits[16 tok x 32 slots (this half)], K=128 ----
        float lacc[4][4];
#pragma unroll
        for (int nt = 0; nt < 4; nt++)
#pragma unroll
            for (int r = 0; r < 4; r++) lacc[nt][r] = 0.f;
#pragma unroll
        for (int ks = 0; ks < 8; ks++) {
            uint32_t ah[4], al[4];
            LDSM_X4(ah, smb + OFF_A1H + offA1_lm + ks*32);
            LDSM_X4(al, smb + OFF_A1L + offA1_lm + ks*32);
#pragma unroll
            for (int p = 0; p < 2; p++) {
                const uint32_t bo = offB1t4 + ks*2304 + (h*2 + p)*32;
                uint32_t bh[4], bl[4];
                LDSM_X4T(bh, b2h + bo);
                LDSM_X4T(bl, b2l + bo);
                mma16816(lacc[2*p],   ah, bh[0], bh[1]);
                mma16816(lacc[2*p],   ah, bl[0], bl[1]);
                mma16816(lacc[2*p],   al, bh[0], bh[1]);
                mma16816(lacc[2*p+1], ah, bh[2], bh[3]);
                mma16816(lacc[2*p+1], ah, bl[2], bl[3]);
                mma16816(lacc[2*p+1], al, bh[2], bh[3]);
            }
        }

        // ---- exp + pack attn A-fragments (K halves of this warp's 32 slots) ----
        const float sv0 = segS[(row0 + g)*25 + ch] * invs;
        const float sv1 = segS[(row0 + g + 8)*25 + ch] * invs;
        uint32_t aHf[2][4], aLf[2][4];
#pragma unroll
        for (int nt = 0; nt < 4; nt++) {
            const float p0 = __expf(lacc[nt][0]*sv0);
            const float p1 = __expf(lacc[nt][1]*sv0);
            const float p2 = __expf(lacc[nt][2]*sv1);
            const float p3 = __expf(lacc[nt][3]*sv1);
            psum0 += p0 + p1;  psum1 += p2 + p3;
            __nv_bfloat16 h0,l0,h1,l1,h2,l2,h3,l3;
            hilo(p0,h0,l0); hilo(p1,h1,l1); hilo(p2,h2,l2); hilo(p3,h3,l3);
            const int ks2 = nt >> 1, hf = nt & 1;
            aHf[ks2][hf*2 + 0] = pack2(h0, h1);
            aHf[ks2][hf*2 + 1] = pack2(h2, h3);
            aLf[ks2][hf*2 + 0] = pack2(l0, l1);
            aLf[ks2][hf*2 + 1] = pack2(l2, l3);
        }

        // ---- MMA2: rec[16 tok x 128 d] += attn @ mem, K = this half's 32 slots ----
#pragma unroll
        for (int ks2 = 0; ks2 < 2; ks2++) {
            const uint32_t kbyte = h*64 + ks2*32;
#pragma unroll
            for (int q = 0; q < 8; q++) {
                const uint32_t bo = offB2n4 + q*2304 + kbyte;
                uint32_t bh[4], bl[4];
                LDSM_X4(bh, b2h + bo);
                LDSM_X4(bl, b2l + bo);
                mma16816(racc[2*q],   aHf[ks2], bh[0], bh[1]);
                mma16816(racc[2*q],   aHf[ks2], bl[0], bl[1]);
                mma16816(racc[2*q],   aLf[ks2], bh[0], bh[1]);
                mma16816(racc[2*q+1], aHf[ks2], bh[2], bh[3]);
                mma16816(racc[2*q+1], aHf[ks2], bl[2], bl[3]);
                mma16816(racc[2*q+1], aLf[ks2], bh[2], bh[3]);
            }
        }
    }

    // quad-reduce psums (over t lanes)
    psum0 += __shfl_xor_sync(0xffffffffu, psum0, 1);
    psum0 += __shfl_xor_sync(0xffffffffu, psum0, 2);
    psum1 += __shfl_xor_sync(0xffffffffu, psum1, 1);
    psum1 += __shfl_xor_sync(0xffffffffu, psum1, 2);

    __syncthreads();   // all MMA2 done: B2 region reusable for racc exchange
    float* rs = (float*)(sm + OFF_B2H0);   // [128 tok][130] floats
    if (h == 1) {
        if (t == 0) { psumP[row0 + g] = psum0; psumP[row0 + g + 8] = psum1; }
#pragma unroll
        for (int nt = 0; nt < 16; nt++) {
            const int c = nt*8 + t*2;
            *(float2*)&rs[(row0 + g)*130 + c]     = float2{racc[nt][0], racc[nt][1]};
            *(float2*)&rs[(row0 + g + 8)*130 + c] = float2{racc[nt][2], racc[nt][3]};
        }
    }
    __syncthreads();

    if (h == 0) {
        const float inv0 = 1.f / (psum0 + psumP[row0 + g]);
        const float inv1 = 1.f / (psum1 + psumP[row0 + g + 8]);
        float lossloc = 0.f;
        const int r0g = row0 + g, r1g = row0 + g + 8;
#pragma unroll
        for (int nt = 0; nt < 16; nt++) {
            const int c = nt*8 + t*2;
            const float2 o0 = *(const float2*)&rs[r0g*130 + c];
            const float2 o1 = *(const float2*)&rs[r1g*130 + c];
            const float rec00 = (racc[nt][0] + o0.x)*inv0, rec01 = (racc[nt][1] + o0.y)*inv0;
            const float rec10 = (racc[nt][2] + o1.x)*inv1, rec11 = (racc[nt][3] + o1.y)*inv1;
            const __nv_bfloat162 ph0 = *(const __nv_bfloat162*)&A1H[r0g*136 + c];
            const __nv_bfloat162 pl0 = *(const __nv_bfloat162*)&A1L[r0g*136 + c];
            const __nv_bfloat162 ph1 = *(const __nv_bfloat162*)&A1H[r1g*136 + c];
            const __nv_bfloat162 pl1 = *(const __nv_bfloat162*)&A1L[r1g*136 + c];
            const float d0 = rec00 - (__bfloat162float(ph0.x) + __bfloat162float(pl0.x));
            const float d1 = rec01 - (__bfloat162float(ph0.y) + __bfloat162float(pl0.y));
            const float d2 = rec10 - (__bfloat162float(ph1.x) + __bfloat162float(pl1.x));
            const float d3 = rec11 - (__bfloat162float(ph1.y) + __bfloat162float(pl1.y));
            lossloc += d0*d0 + d1*d1 + d2*d2 + d3*d3;
            atomicMax(&dmax[c],     encf(fmaxf(rec00, rec10)));
            atomicMax(&dmax[c + 1], encf(fmaxf(rec01, rec11)));
        }
#pragma unroll
        for (int o = 16; o > 0; o >>= 1)
            lossloc += __shfl_xor_sync(0xffffffffu, lossloc, o);
        if (lane == 0) wsum[wid] = lossloc;
    }
    __syncthreads();
    if (tid < FDC) atomicMax(&g_skl[b*FDC + tid], dmax[tid]);
    if (tid == 0) {
        float s = 0.f;
        for (int w = 0; w < 8; w++) s += wsum[w];
        g_lossPartial[blockIdx.x] = s;
    }
}

// =====================================================================
// Kernel C: 4 blocks (one per batch); block 0 also finalizes loss
// =====================================================================
__global__ __launch_bounds__(256) void kC(const float* __restrict__ ln_g,
        const float* __restrict__ ln_b, const float* __restrict__ w1,
        const float* __restrict__ b1,   const float* __restrict__ w2,
        const float* __restrict__ b2,   float* __restrict__ out)
{
    __shared__ float red[128];
    __shared__ float hbuf[128];
    __shared__ float h2[64];
    __shared__ float wsum2[8];
    const int tid = threadIdx.x;
    const int b   = blockIdx.x;

    if (b == 0) {
        float s = 0.f;
        for (int i = tid; i < NBLK_B; i += 256) s += g_lossPartial[i];
#pragma unroll
        for (int o = 16; o > 0; o >>= 1) s += __shfl_xor_sync(0xffffffffu, s, o);
        if ((tid & 31) == 0) wsum2[tid >> 5] = s;
        __syncthreads();
        if (tid == 0) {
            float tt = 0.f;
            for (int w = 0; w < 8; w++) tt += wsum2[w];
            out[LOSS_OFF] = tt / ((float)TOK * (float)FDC);
        }
    }

    float x = 0.f;
    if (tid < FDC) { x = decf(g_skl[b*FDC + tid]); red[tid] = x; }
    __syncthreads();
    for (int o = 64; o > 0; o >>= 1) {
        if (tid < o) red[tid] += red[tid + o];
        __syncthreads();
    }
    const float mu = red[0] * (1.f/FDC);
    __syncthreads();
    const float dfx = x - mu;
    if (tid < FDC) red[tid] = dfx*dfx;
    __syncthreads();
    for (int o = 64; o > 0; o >>= 1) {
        if (tid < o) red[tid] += red[tid + o];
        __syncthreads();
    }
    const float var = red[0] * (1.f/FDC);
    __syncthreads();
    if (tid < FDC)
        hbuf[tid] = dfx * rsqrtf(var + 1e-5f) * ln_g[tid] + ln_b[tid];
    __syncthreads();
    if (tid < FDC/2) {
        float a = b1[tid];
        for (int d = 0; d < FDC; ++d) a = fmaf(hbuf[d], w1[tid*FDC + d], a);
        h2[tid] = 0.5f * a * (1.f + erff(a * 0.70710678118654752f));
    }
    __syncthreads();
    if (tid < OUTC) {
        float a = b2[tid];
        for (int e = 0; e < FDC/2; ++e) a = fmaf(h2[e], w2[tid*(FDC/2) + e], a);
        out[b*OUTC + tid] = a;
    }
}

extern "C" void kernel_launch(void* const* d_in, const int* in_sizes, int n_in,
                              void* d_out, int out_size)
{
    const float* feat  = (const float*)d_in[0];
    const float* seg_w = (const float*)d_in[1];
    const float* seg_b = (const float*)d_in[2];
    const float* pc_w  = (const float*)d_in[3];
    const float* pc_b  = (const float*)d_in[4];
    const float* memw  = (const float*)d_in[5];
    const float* ln_g  = (const float*)d_in[6];
    const float* ln_b  = (const float*)d_in[7];
    const float* w1    = (const float*)d_in[8];
    const float* b1    = (const float*)d_in[9];
    const float* w2    = (const float*)d_in[10];
    const float* b2    = (const float*)d_in[11];
    float* out = (float*)d_out;

    cudaFuncSetAttribute(kA, cudaFuncAttributeMaxDynamicSharedMemorySize, 2*KA_BUF);
    cudaFuncSetAttribute(kB, cudaFuncAttributeMaxDynamicSharedMemorySize, SMEM_B_TOTAL);

    kInit<<<1, 512>>>();
    kPrep<<<(FDC*JJ*MMS + 255)/256, 256>>>(memw);
    kPrepW<<<(32*160*32 + 255)/256, 256>>>(seg_w, pc_w);
    kA<<<TOK/128, 256, 2*KA_BUF>>>(feat, seg_b, pc_b, out);
    kB<<<NBLK_B, 512, SMEM_B_TOTAL>>>(out + SEG_OFF);
    kC<<<4, 256>>>(ln_g, ln_b, w1, b1, w2, b2, out);
}